// round 1
// baseline (speedup 1.0000x reference)
#include <cuda_runtime.h>
#include <cuda_bf16.h>
#include <mma.h>
#include <cstdint>

using namespace nvcuda;

// Problem constants
#define BATCH 4
#define SEQ   2048
#define DIM   1024
#define HEADS 16
#define HDIM  64
#define MROWS (BATCH*SEQ)          // 8192

// Scratch (device globals; no runtime allocation allowed)
__device__ float g_qkv[(size_t)3 * BATCH * HEADS * SEQ * HDIM];   // [which][b][h][s][hd]
__device__ float g_attn[(size_t)BATCH * SEQ * DIM];               // [b][s][h*64+hd]

// ---------------------------------------------------------------------------
// TF32 WMMA GEMM: C[M,N] = A[M,K] @ B[K,N] + bias[N]
// BM=128, BN=128, BK=32; 256 threads = 8 warps (2x4 of 64x32 warp tiles)
// mode 1: A = x (arg), scatter output into g_qkv
// mode 2: A = g_attn,  plain row-major output into C
// ---------------------------------------------------------------------------
#define GBM 128
#define GBN 128
#define GBK 32
#define LDA 36    // GBK + 4
#define LDB 132   // GBN + 4
#define LDC 132
#define GEMM_SMEM (16896 * 4)   // 128*132 floats staging (>= As+Bs working set)

__global__ __launch_bounds__(256) void gemm_tf32(
    const float* __restrict__ A, const float* __restrict__ B,
    const float* __restrict__ bias, float* __restrict__ C,
    int M, int N, int K, int mode)
{
    extern __shared__ float smem[];
    float* As = smem;                 // [128][36]
    float* Bs = smem + GBM * LDA;     // [32][132]

    if (mode == 2) A = g_attn;

    const int tid  = threadIdx.x;
    const int warp = tid >> 5;
    const int wm   = warp >> 2;       // 0..1
    const int wn   = warp & 3;        // 0..3
    const int m0   = blockIdx.y * GBM;
    const int n0   = blockIdx.x * GBN;

    wmma::fragment<wmma::accumulator, 16, 16, 8, float> acc[4][2];
    #pragma unroll
    for (int i = 0; i < 4; i++)
        #pragma unroll
        for (int j = 0; j < 2; j++)
            wmma::fill_fragment(acc[i][j], 0.0f);

    for (int k0 = 0; k0 < K; k0 += GBK) {
        // Load A tile: 128x32 floats = 1024 float4
        #pragma unroll
        for (int i = 0; i < 4; i++) {
            int idx = tid + i * 256;
            int r = idx >> 3, c4 = idx & 7;
            float4 v = *reinterpret_cast<const float4*>(
                A + (size_t)(m0 + r) * K + k0 + c4 * 4);
            *reinterpret_cast<float4*>(&As[r * LDA + c4 * 4]) = v;
        }
        // Load B tile: 32x128 floats = 1024 float4
        #pragma unroll
        for (int i = 0; i < 4; i++) {
            int idx = tid + i * 256;
            int r = idx >> 5, c4 = idx & 31;
            float4 v = *reinterpret_cast<const float4*>(
                B + (size_t)(k0 + r) * N + n0 + c4 * 4);
            *reinterpret_cast<float4*>(&Bs[r * LDB + c4 * 4]) = v;
        }
        __syncthreads();

        #pragma unroll
        for (int kk = 0; kk < GBK; kk += 8) {
            wmma::fragment<wmma::matrix_a, 16, 16, 8, wmma::precision::tf32, wmma::row_major> af[4];
            wmma::fragment<wmma::matrix_b, 16, 16, 8, wmma::precision::tf32, wmma::row_major> bf[2];
            #pragma unroll
            for (int i = 0; i < 4; i++) {
                wmma::load_matrix_sync(af[i], &As[(wm * 64 + i * 16) * LDA + kk], LDA);
                #pragma unroll
                for (int t = 0; t < af[i].num_elements; t++)
                    af[i].x[t] = wmma::__float_to_tf32(af[i].x[t]);
            }
            #pragma unroll
            for (int j = 0; j < 2; j++) {
                wmma::load_matrix_sync(bf[j], &Bs[kk * LDB + wn * 32 + j * 16], LDB);
                #pragma unroll
                for (int t = 0; t < bf[j].num_elements; t++)
                    bf[j].x[t] = wmma::__float_to_tf32(bf[j].x[t]);
            }
            #pragma unroll
            for (int i = 0; i < 4; i++)
                #pragma unroll
                for (int j = 0; j < 2; j++)
                    wmma::mma_sync(acc[i][j], af[i], bf[j], acc[i][j]);
        }
        __syncthreads();
    }

    // Epilogue: stage to shared (reuses As/Bs space), add bias, write out.
    float* Csh = smem;   // [128][132]
    #pragma unroll
    for (int i = 0; i < 4; i++)
        #pragma unroll
        for (int j = 0; j < 2; j++)
            wmma::store_matrix_sync(&Csh[(wm * 64 + i * 16) * LDC + wn * 32 + j * 16],
                                    acc[i][j], LDC, wmma::mem_row_major);
    __syncthreads();

    #pragma unroll
    for (int i = 0; i < 16; i++) {
        int idx = tid + i * 256;         // 0..4095 float4s
        int r = idx >> 5;                // row 0..127
        int c = (idx & 31) * 4;          // col 0..124
        float4 v = *reinterpret_cast<float4*>(&Csh[r * LDC + c]);
        int gm = m0 + r;
        int gn = n0 + c;
        v.x += bias[gn];
        v.y += bias[gn + 1];
        v.z += bias[gn + 2];
        v.w += bias[gn + 3];
        if (mode == 1) {
            // scatter into g_qkv[which][b][h][s][hd]
            int which = gn >> 10;
            int d = gn & 1023;
            int h = d >> 6;
            int hd = d & 63;
            int b = gm >> 11;
            int s = gm & 2047;
            float* dst = &g_qkv[((((size_t)which * BATCH + b) * HEADS + h) * SEQ + s) * HDIM + hd];
            *reinterpret_cast<float4*>(dst) = v;
        } else {
            *reinterpret_cast<float4*>(&C[(size_t)gm * N + gn]) = v;
        }
    }
}

// ---------------------------------------------------------------------------
// Flash attention: one CTA per (q-tile of 64, b*h). 128 threads = 4 warps.
// TF32 WMMA for S = Q@K^T and O += P@V; online softmax, causal optional.
// ---------------------------------------------------------------------------
#define FLDS 68                        // 64 + 4 pad
#define FLASH_SMEM ((5 * 64 * FLDS + 128) * 4)

__global__ __launch_bounds__(128) void flash_attn(
    const int* __restrict__ flag_ptr, float* __restrict__ attn_out)
{
    extern __shared__ float sm[];
    float* Qs   = sm;                    // [64][68]
    float* Ks   = Qs + 64 * FLDS;
    float* Vs   = Ks + 64 * FLDS;
    float* Ss   = Vs + 64 * FLDS;
    float* Os   = Ss + 64 * FLDS;
    float* mrow = Os + 64 * FLDS;        // [64]
    float* lrow = mrow + 64;             // [64]

    const int qt   = blockIdx.x;
    const int bh   = blockIdx.y;
    const int b    = bh >> 4;
    const int h    = bh & 15;
    const int tid  = threadIdx.x;
    const int warp = tid >> 5;
    const float scale = 0.125f;          // 1/sqrt(64)

    // Load Q tile (64x64)
    const float* qg = g_qkv + ((((size_t)0 * BATCH + b) * HEADS + h) * SEQ + qt * 64) * HDIM;
    #pragma unroll
    for (int i = 0; i < 8; i++) {
        int idx = tid + i * 128;
        int r = idx >> 4, c = (idx & 15) * 4;
        float4 v = *reinterpret_cast<const float4*>(qg + r * 64 + c);
        *reinterpret_cast<float4*>(&Qs[r * FLDS + c]) = v;
        // zero O with same indexing
        *reinterpret_cast<float4*>(&Os[r * FLDS + c]) = make_float4(0.f, 0.f, 0.f, 0.f);
    }
    if (tid < 64) { mrow[tid] = -1e30f; lrow[tid] = 0.0f; }
    __syncthreads();

    const int causal = *flag_ptr;
    const int ktmax = causal ? qt : (SEQ / 64 - 1);

    const float* kgbase = g_qkv + ((((size_t)1 * BATCH + b) * HEADS + h) * SEQ) * HDIM;
    const float* vgbase = g_qkv + ((((size_t)2 * BATCH + b) * HEADS + h) * SEQ) * HDIM;

    for (int kt = 0; kt <= ktmax; kt++) {
        // Load K,V tiles
        const float* kg = kgbase + (size_t)kt * 64 * HDIM;
        const float* vg = vgbase + (size_t)kt * 64 * HDIM;
        #pragma unroll
        for (int i = 0; i < 8; i++) {
            int idx = tid + i * 128;
            int r = idx >> 4, c = (idx & 15) * 4;
            *reinterpret_cast<float4*>(&Ks[r * FLDS + c]) =
                *reinterpret_cast<const float4*>(kg + r * 64 + c);
            *reinterpret_cast<float4*>(&Vs[r * FLDS + c]) =
                *reinterpret_cast<const float4*>(vg + r * 64 + c);
        }
        __syncthreads();

        // S = Q @ K^T   (each warp: 16 rows x 64 cols)
        {
            wmma::fragment<wmma::accumulator, 16, 16, 8, float> sacc[4];
            #pragma unroll
            for (int j = 0; j < 4; j++) wmma::fill_fragment(sacc[j], 0.0f);
            #pragma unroll
            for (int d0 = 0; d0 < 64; d0 += 8) {
                wmma::fragment<wmma::matrix_a, 16, 16, 8, wmma::precision::tf32, wmma::row_major> af;
                wmma::load_matrix_sync(af, &Qs[warp * 16 * FLDS + d0], FLDS);
                #pragma unroll
                for (int t = 0; t < af.num_elements; t++)
                    af.x[t] = wmma::__float_to_tf32(af.x[t]);
                #pragma unroll
                for (int j = 0; j < 4; j++) {
                    wmma::fragment<wmma::matrix_b, 16, 16, 8, wmma::precision::tf32, wmma::col_major> bf;
                    // K^T(d,k) = Ks[k][d]  -> col-major with ldm = FLDS
                    wmma::load_matrix_sync(bf, &Ks[(j * 16) * FLDS + d0], FLDS);
                    #pragma unroll
                    for (int t = 0; t < bf.num_elements; t++)
                        bf.x[t] = wmma::__float_to_tf32(bf.x[t]);
                    wmma::mma_sync(sacc[j], af, bf, sacc[j]);
                }
            }
            #pragma unroll
            for (int j = 0; j < 4; j++)
                wmma::store_matrix_sync(&Ss[warp * 16 * FLDS + j * 16], sacc[j],
                                        FLDS, wmma::mem_row_major);
        }
        __syncthreads();

        // Online softmax: one thread per query row
        if (tid < 64) {
            int r = tid;
            int nvalid = (causal && kt == qt) ? (r + 1) : 64;
            float mold = mrow[r];
            float mnew = mold;
            #pragma unroll 4
            for (int j = 0; j < nvalid; j++) {
                float s = Ss[r * FLDS + j] * scale;
                Ss[r * FLDS + j] = s;
                mnew = fmaxf(mnew, s);
            }
            float alpha = __expf(mold - mnew);
            float sum = 0.0f;
            #pragma unroll 4
            for (int j = 0; j < nvalid; j++) {
                float p = __expf(Ss[r * FLDS + j] - mnew);
                Ss[r * FLDS + j] = p;
                sum += p;
            }
            for (int j = nvalid; j < 64; j++) Ss[r * FLDS + j] = 0.0f;
            lrow[r] = lrow[r] * alpha + sum;
            mrow[r] = mnew;
            #pragma unroll 8
            for (int d = 0; d < 64; d++) Os[r * FLDS + d] *= alpha;
        }
        __syncthreads();

        // O += P @ V
        {
            wmma::fragment<wmma::accumulator, 16, 16, 8, float> oacc[4];
            #pragma unroll
            for (int j = 0; j < 4; j++)
                wmma::load_matrix_sync(oacc[j], &Os[warp * 16 * FLDS + j * 16],
                                       FLDS, wmma::mem_row_major);
            #pragma unroll
            for (int k0 = 0; k0 < 64; k0 += 8) {
                wmma::fragment<wmma::matrix_a, 16, 16, 8, wmma::precision::tf32, wmma::row_major> af;
                wmma::load_matrix_sync(af, &Ss[warp * 16 * FLDS + k0], FLDS);
                #pragma unroll
                for (int t = 0; t < af.num_elements; t++)
                    af.x[t] = wmma::__float_to_tf32(af.x[t]);
                #pragma unroll
                for (int j = 0; j < 4; j++) {
                    wmma::fragment<wmma::matrix_b, 16, 16, 8, wmma::precision::tf32, wmma::row_major> bf;
                    wmma::load_matrix_sync(bf, &Vs[k0 * FLDS + j * 16], FLDS);
                    #pragma unroll
                    for (int t = 0; t < bf.num_elements; t++)
                        bf.x[t] = wmma::__float_to_tf32(bf.x[t]);
                    wmma::mma_sync(oacc[j], af, bf, oacc[j]);
                }
            }
            #pragma unroll
            for (int j = 0; j < 4; j++)
                wmma::store_matrix_sync(&Os[warp * 16 * FLDS + j * 16], oacc[j],
                                        FLDS, wmma::mem_row_major);
        }
        __syncthreads();
    }

    // Epilogue: O / l -> g_attn[b][s][h*64+hd]
    if (tid < 64) {
        int r = tid;
        float inv = 1.0f / lrow[r];
        int sg = qt * 64 + r;
        float* dst = attn_out + ((size_t)b * SEQ + sg) * DIM + h * HDIM;
        #pragma unroll 8
        for (int d = 0; d < 64; d++)
            dst[d] = Os[r * FLDS + d] * inv;
    }
}

// ---------------------------------------------------------------------------
extern "C" void kernel_launch(void* const* d_in, const int* in_sizes, int n_in,
                              void* d_out, int out_size)
{
    const float* x     = (const float*)d_in[0];
    const float* Wqkv  = (const float*)d_in[1];
    const float* bqkv  = (const float*)d_in[2];
    const float* Wout  = (const float*)d_in[3];
    const float* bout  = (const float*)d_in[4];
    const int*   flag  = (const int*)d_in[5];
    float*       out   = (float*)d_out;

    cudaFuncSetAttribute(gemm_tf32, cudaFuncAttributeMaxDynamicSharedMemorySize, GEMM_SMEM);
    cudaFuncSetAttribute(flash_attn, cudaFuncAttributeMaxDynamicSharedMemorySize, FLASH_SMEM);

    // get device address of g_attn for flash epilogue target
    float* attn_ptr = nullptr;
    cudaGetSymbolAddress((void**)&attn_ptr, g_attn);

    // 1) QKV projection -> scatter to g_qkv
    dim3 g1(3 * DIM / GBN, MROWS / GBM);     // (24, 64)
    gemm_tf32<<<g1, 256, GEMM_SMEM>>>(x, Wqkv, bqkv, nullptr, MROWS, 3 * DIM, DIM, 1);

    // 2) Flash attention -> g_attn
    dim3 g2(SEQ / 64, BATCH * HEADS);        // (32, 64)
    flash_attn<<<g2, 128, FLASH_SMEM>>>(flag, attn_ptr);

    // 3) Output projection -> d_out
    dim3 g3(DIM / GBN, MROWS / GBM);         // (8, 64)
    gemm_tf32<<<g3, 256, GEMM_SMEM>>>(nullptr, Wout, bout, out, MROWS, DIM, DIM, 2);
}

// round 2
// speedup vs baseline: 1.1108x; 1.1108x over previous
#include <cuda_runtime.h>
#include <cuda_bf16.h>
#include <mma.h>
#include <cstdint>

using namespace nvcuda;

// Problem constants
#define BATCH 4
#define SEQ   2048
#define DIM   1024
#define HEADS 16
#define HDIM  64
#define MROWS (BATCH*SEQ)          // 8192

// Scratch (device globals; no runtime allocation allowed)
__device__ float g_qkv[(size_t)3 * BATCH * HEADS * SEQ * HDIM];   // [which][b][h][s][hd]
__device__ float g_attn[(size_t)BATCH * SEQ * DIM];               // [b][s][h*64+hd]

// ---------------------------------------------------------------------------
// cp.async helpers
// ---------------------------------------------------------------------------
__device__ __forceinline__ void cp_async16(void* smem_dst, const void* gmem_src) {
    uint32_t s = (uint32_t)__cvta_generic_to_shared(smem_dst);
    asm volatile("cp.async.cg.shared.global [%0], [%1], 16;\n" :: "r"(s), "l"(gmem_src));
}
#define CP_COMMIT() asm volatile("cp.async.commit_group;\n" ::: "memory")
#define CP_WAIT(n)  asm volatile("cp.async.wait_group %0;\n" :: "n"(n) : "memory")

// ---------------------------------------------------------------------------
// TF32 WMMA GEMM: C[M,N] = A[M,K] @ B[K,N] + bias[N]
// BM=128, BN=128, BK=32; 256 threads = 8 warps (2x4 of 64x32 warp tiles)
// Double-buffered cp.async pipeline.
// mode 1: scatter output into g_qkv; mode 2: plain row-major into C
// ---------------------------------------------------------------------------
#define GBM 128
#define GBN 128
#define GBK 32
#define LDA 36    // GBK + 4
#define LDB 132   // GBN + 4
#define LDC 132
#define ASZ (GBM * LDA)           // 4608 floats
#define BSZ (GBK * LDB)           // 4224 floats
#define STAGE_SZ (ASZ + BSZ)      // 8832 floats
#define GEMM_SMEM (2 * STAGE_SZ * 4)   // 70656 B (epilogue needs 67584 B, fits)

__device__ __forceinline__ void gemm_prefetch(
    const float* __restrict__ A, const float* __restrict__ B,
    float* As, float* Bs, int K, int N, int m0, int n0, int k0, int tid)
{
    #pragma unroll
    for (int i = 0; i < 4; i++) {
        int idx = tid + i * 256;
        int r = idx >> 3, c4 = idx & 7;
        cp_async16(&As[r * LDA + c4 * 4], A + (size_t)(m0 + r) * K + k0 + c4 * 4);
    }
    #pragma unroll
    for (int i = 0; i < 4; i++) {
        int idx = tid + i * 256;
        int r = idx >> 5, c4 = idx & 31;
        cp_async16(&Bs[r * LDB + c4 * 4], B + (size_t)(k0 + r) * N + n0 + c4 * 4);
    }
}

__global__ __launch_bounds__(256, 2) void gemm_tf32(
    const float* __restrict__ A, const float* __restrict__ B,
    const float* __restrict__ bias, float* __restrict__ C,
    int M, int N, int K, int mode)
{
    extern __shared__ float smem[];
    float* Abuf[2] = { smem, smem + STAGE_SZ };
    float* Bbuf[2] = { smem + ASZ, smem + STAGE_SZ + ASZ };

    const int tid  = threadIdx.x;
    const int warp = tid >> 5;
    const int wm   = warp >> 2;       // 0..1
    const int wn   = warp & 3;        // 0..3
    const int m0   = blockIdx.y * GBM;
    const int n0   = blockIdx.x * GBN;

    wmma::fragment<wmma::accumulator, 16, 16, 8, float> acc[4][2];
    #pragma unroll
    for (int i = 0; i < 4; i++)
        #pragma unroll
        for (int j = 0; j < 2; j++)
            wmma::fill_fragment(acc[i][j], 0.0f);

    const int nk = K / GBK;
    gemm_prefetch(A, B, Abuf[0], Bbuf[0], K, N, m0, n0, 0, tid);
    CP_COMMIT();

    for (int t = 0; t < nk; t++) {
        if (t + 1 < nk) {
            gemm_prefetch(A, B, Abuf[(t + 1) & 1], Bbuf[(t + 1) & 1],
                          K, N, m0, n0, (t + 1) * GBK, tid);
            CP_COMMIT();
            CP_WAIT(1);
        } else {
            CP_WAIT(0);
        }
        __syncthreads();

        const float* As = Abuf[t & 1];
        const float* Bs = Bbuf[t & 1];
        #pragma unroll
        for (int kk = 0; kk < GBK; kk += 8) {
            wmma::fragment<wmma::matrix_a, 16, 16, 8, wmma::precision::tf32, wmma::row_major> af[4];
            wmma::fragment<wmma::matrix_b, 16, 16, 8, wmma::precision::tf32, wmma::row_major> bf[2];
            #pragma unroll
            for (int i = 0; i < 4; i++) {
                wmma::load_matrix_sync(af[i], &As[(wm * 64 + i * 16) * LDA + kk], LDA);
                #pragma unroll
                for (int t2 = 0; t2 < af[i].num_elements; t2++)
                    af[i].x[t2] = wmma::__float_to_tf32(af[i].x[t2]);
            }
            #pragma unroll
            for (int j = 0; j < 2; j++) {
                wmma::load_matrix_sync(bf[j], &Bs[kk * LDB + wn * 32 + j * 16], LDB);
                #pragma unroll
                for (int t2 = 0; t2 < bf[j].num_elements; t2++)
                    bf[j].x[t2] = wmma::__float_to_tf32(bf[j].x[t2]);
            }
            #pragma unroll
            for (int i = 0; i < 4; i++)
                #pragma unroll
                for (int j = 0; j < 2; j++)
                    wmma::mma_sync(acc[i][j], af[i], bf[j], acc[i][j]);
        }
        __syncthreads();
    }

    // Epilogue: stage to shared (reuses pipeline smem), add bias, write out.
    float* Csh = smem;   // [128][132] = 67584 B < 70656 B
    #pragma unroll
    for (int i = 0; i < 4; i++)
        #pragma unroll
        for (int j = 0; j < 2; j++)
            wmma::store_matrix_sync(&Csh[(wm * 64 + i * 16) * LDC + wn * 32 + j * 16],
                                    acc[i][j], LDC, wmma::mem_row_major);
    __syncthreads();

    #pragma unroll
    for (int i = 0; i < 16; i++) {
        int idx = tid + i * 256;         // 0..4095 float4s
        int r = idx >> 5;                // row 0..127
        int c = (idx & 31) * 4;          // col 0..124
        float4 v = *reinterpret_cast<float4*>(&Csh[r * LDC + c]);
        int gm = m0 + r;
        int gn = n0 + c;
        v.x += bias[gn];
        v.y += bias[gn + 1];
        v.z += bias[gn + 2];
        v.w += bias[gn + 3];
        if (mode == 1) {
            int which = gn >> 10;
            int d = gn & 1023;
            int h = d >> 6;
            int hd = d & 63;
            int b = gm >> 11;
            int s = gm & 2047;
            float* dst = &g_qkv[((((size_t)which * BATCH + b) * HEADS + h) * SEQ + s) * HDIM + hd];
            *reinterpret_cast<float4*>(dst) = v;
        } else {
            *reinterpret_cast<float4*>(&C[(size_t)gm * N + gn]) = v;
        }
    }
}

// ---------------------------------------------------------------------------
// Flash attention: one CTA per (q-tile of 64, b*h). 128 threads = 4 warps.
// TF32 WMMA for S = Q@K^T and O += P@V.
// Softmax fully parallel: 2 threads per row, float4-vectorized, shuffle merge.
// Scale 1/sqrt(64) folded into Q at load.
// ---------------------------------------------------------------------------
#define FLDS 68                        // 64 + 4 pad
#define FLASH_SMEM ((5 * 64 * FLDS + 128) * 4)   // ~87.5 KB -> 2 CTAs/SM

__global__ __launch_bounds__(128) void flash_attn(
    const int* __restrict__ flag_ptr, float* __restrict__ attn_out)
{
    extern __shared__ float sm[];
    float* Qs   = sm;                    // [64][68]
    float* Ks   = Qs + 64 * FLDS;
    float* Vs   = Ks + 64 * FLDS;
    float* Ss   = Vs + 64 * FLDS;
    float* Os   = Ss + 64 * FLDS;
    float* mrow = Os + 64 * FLDS;        // [64]
    float* lrow = mrow + 64;             // [64]

    const int qt   = blockIdx.x;
    const int bh   = blockIdx.y;
    const int b    = bh >> 4;
    const int h    = bh & 15;
    const int tid  = threadIdx.x;
    const int warp = tid >> 5;

    // Load Q tile (64x64), pre-scaled by 1/sqrt(HD); zero O.
    const float* qg = g_qkv + ((((size_t)0 * BATCH + b) * HEADS + h) * SEQ + qt * 64) * HDIM;
    #pragma unroll
    for (int i = 0; i < 8; i++) {
        int idx = tid + i * 128;
        int r = idx >> 4, c = (idx & 15) * 4;
        float4 v = *reinterpret_cast<const float4*>(qg + r * 64 + c);
        v.x *= 0.125f; v.y *= 0.125f; v.z *= 0.125f; v.w *= 0.125f;
        *reinterpret_cast<float4*>(&Qs[r * FLDS + c]) = v;
        *reinterpret_cast<float4*>(&Os[r * FLDS + c]) = make_float4(0.f, 0.f, 0.f, 0.f);
    }
    if (tid < 64) { mrow[tid] = -1e30f; lrow[tid] = 0.0f; }
    __syncthreads();

    const int causal = *flag_ptr;
    const int ktmax = causal ? qt : (SEQ / 64 - 1);

    const float* kgbase = g_qkv + ((((size_t)1 * BATCH + b) * HEADS + h) * SEQ) * HDIM;
    const float* vgbase = g_qkv + ((((size_t)2 * BATCH + b) * HEADS + h) * SEQ) * HDIM;

    // Softmax thread mapping: 2 threads per row
    const int srow_r  = tid >> 1;
    const int srow_hf = tid & 1;
    float* srow = &Ss[srow_r * FLDS + srow_hf * 32];
    float* orow = &Os[srow_r * FLDS + srow_hf * 32];

    for (int kt = 0; kt <= ktmax; kt++) {
        // Load K,V tiles
        const float* kg = kgbase + (size_t)kt * 64 * HDIM;
        const float* vg = vgbase + (size_t)kt * 64 * HDIM;
        #pragma unroll
        for (int i = 0; i < 8; i++) {
            int idx = tid + i * 128;
            int r = idx >> 4, c = (idx & 15) * 4;
            *reinterpret_cast<float4*>(&Ks[r * FLDS + c]) =
                *reinterpret_cast<const float4*>(kg + r * 64 + c);
            *reinterpret_cast<float4*>(&Vs[r * FLDS + c]) =
                *reinterpret_cast<const float4*>(vg + r * 64 + c);
        }
        __syncthreads();

        // S = Q @ K^T   (each warp: 16 rows x 64 cols)
        {
            wmma::fragment<wmma::accumulator, 16, 16, 8, float> sacc[4];
            #pragma unroll
            for (int j = 0; j < 4; j++) wmma::fill_fragment(sacc[j], 0.0f);
            #pragma unroll
            for (int d0 = 0; d0 < 64; d0 += 8) {
                wmma::fragment<wmma::matrix_a, 16, 16, 8, wmma::precision::tf32, wmma::row_major> af;
                wmma::load_matrix_sync(af, &Qs[warp * 16 * FLDS + d0], FLDS);
                #pragma unroll
                for (int t = 0; t < af.num_elements; t++)
                    af.x[t] = wmma::__float_to_tf32(af.x[t]);
                #pragma unroll
                for (int j = 0; j < 4; j++) {
                    wmma::fragment<wmma::matrix_b, 16, 16, 8, wmma::precision::tf32, wmma::col_major> bf;
                    wmma::load_matrix_sync(bf, &Ks[(j * 16) * FLDS + d0], FLDS);
                    #pragma unroll
                    for (int t = 0; t < bf.num_elements; t++)
                        bf.x[t] = wmma::__float_to_tf32(bf.x[t]);
                    wmma::mma_sync(sacc[j], af, bf, sacc[j]);
                }
            }
            #pragma unroll
            for (int j = 0; j < 4; j++)
                wmma::store_matrix_sync(&Ss[warp * 16 * FLDS + j * 16], sacc[j],
                                        FLDS, wmma::mem_row_major);
        }
        __syncthreads();

        // Online softmax: 2 threads per row, 32 cols each (8x float4)
        {
            const int nvalid = (causal && kt == qt) ? (srow_r + 1) : 64;
            const int cbase  = srow_hf * 32;
            const float mold = mrow[srow_r];
            const float lold = lrow[srow_r];

            float4 sv[8];
            float mloc = -1e30f;
            #pragma unroll
            for (int j = 0; j < 8; j++) {
                float4 v = *reinterpret_cast<float4*>(&srow[j * 4]);
                int c0 = cbase + j * 4;
                v.x = (c0 + 0 < nvalid) ? v.x : -1e30f;
                v.y = (c0 + 1 < nvalid) ? v.y : -1e30f;
                v.z = (c0 + 2 < nvalid) ? v.z : -1e30f;
                v.w = (c0 + 3 < nvalid) ? v.w : -1e30f;
                sv[j] = v;
                mloc = fmaxf(mloc, fmaxf(fmaxf(v.x, v.y), fmaxf(v.z, v.w)));
            }
            float moth = __shfl_xor_sync(0xffffffffu, mloc, 1);
            float mnew = fmaxf(mold, fmaxf(mloc, moth));

            float sum = 0.0f;
            #pragma unroll
            for (int j = 0; j < 8; j++) {
                float4 v = sv[j];
                v.x = __expf(v.x - mnew);
                v.y = __expf(v.y - mnew);
                v.z = __expf(v.z - mnew);
                v.w = __expf(v.w - mnew);
                sum += (v.x + v.y) + (v.z + v.w);
                *reinterpret_cast<float4*>(&srow[j * 4]) = v;
            }
            float soth = __shfl_xor_sync(0xffffffffu, sum, 1);
            sum += soth;

            float alpha = __expf(mold - mnew);
            if (srow_hf == 0) {
                mrow[srow_r] = mnew;
                lrow[srow_r] = lold * alpha + sum;
            }
            // Rescale O (half row per thread)
            #pragma unroll
            for (int j = 0; j < 8; j++) {
                float4 o = *reinterpret_cast<float4*>(&orow[j * 4]);
                o.x *= alpha; o.y *= alpha; o.z *= alpha; o.w *= alpha;
                *reinterpret_cast<float4*>(&orow[j * 4]) = o;
            }
        }
        __syncthreads();

        // O += P @ V
        {
            wmma::fragment<wmma::accumulator, 16, 16, 8, float> oacc[4];
            #pragma unroll
            for (int j = 0; j < 4; j++)
                wmma::load_matrix_sync(oacc[j], &Os[warp * 16 * FLDS + j * 16],
                                       FLDS, wmma::mem_row_major);
            #pragma unroll
            for (int k0 = 0; k0 < 64; k0 += 8) {
                wmma::fragment<wmma::matrix_a, 16, 16, 8, wmma::precision::tf32, wmma::row_major> af;
                wmma::load_matrix_sync(af, &Ss[warp * 16 * FLDS + k0], FLDS);
                #pragma unroll
                for (int t = 0; t < af.num_elements; t++)
                    af.x[t] = wmma::__float_to_tf32(af.x[t]);
                #pragma unroll
                for (int j = 0; j < 4; j++) {
                    wmma::fragment<wmma::matrix_b, 16, 16, 8, wmma::precision::tf32, wmma::row_major> bf;
                    wmma::load_matrix_sync(bf, &Vs[k0 * FLDS + j * 16], FLDS);
                    #pragma unroll
                    for (int t = 0; t < bf.num_elements; t++)
                        bf.x[t] = wmma::__float_to_tf32(bf.x[t]);
                    wmma::mma_sync(oacc[j], af, bf, oacc[j]);
                }
            }
            #pragma unroll
            for (int j = 0; j < 4; j++)
                wmma::store_matrix_sync(&Os[warp * 16 * FLDS + j * 16], oacc[j],
                                        FLDS, wmma::mem_row_major);
        }
        __syncthreads();
    }

    // Epilogue: O / l -> g_attn[b][s][h*64+hd]  (2 threads per row)
    {
        float inv = 1.0f / lrow[srow_r];
        int sg = qt * 64 + srow_r;
        float* dst = attn_out + ((size_t)b * SEQ + sg) * DIM + h * HDIM + srow_hf * 32;
        #pragma unroll
        for (int j = 0; j < 8; j++) {
            float4 o = *reinterpret_cast<float4*>(&orow[j * 4]);
            o.x *= inv; o.y *= inv; o.z *= inv; o.w *= inv;
            *reinterpret_cast<float4*>(&dst[j * 4]) = o;
        }
    }
}

// ---------------------------------------------------------------------------
extern "C" void kernel_launch(void* const* d_in, const int* in_sizes, int n_in,
                              void* d_out, int out_size)
{
    const float* x     = (const float*)d_in[0];
    const float* Wqkv  = (const float*)d_in[1];
    const float* bqkv  = (const float*)d_in[2];
    const float* Wout  = (const float*)d_in[3];
    const float* bout  = (const float*)d_in[4];
    const int*   flag  = (const int*)d_in[5];
    float*       out   = (float*)d_out;

    cudaFuncSetAttribute(gemm_tf32, cudaFuncAttributeMaxDynamicSharedMemorySize, GEMM_SMEM);
    cudaFuncSetAttribute(flash_attn, cudaFuncAttributeMaxDynamicSharedMemorySize, FLASH_SMEM);

    float* attn_ptr = nullptr;
    cudaGetSymbolAddress((void**)&attn_ptr, g_attn);

    // 1) QKV projection -> scatter to g_qkv
    dim3 g1(3 * DIM / GBN, MROWS / GBM);     // (24, 64)
    gemm_tf32<<<g1, 256, GEMM_SMEM>>>(x, Wqkv, bqkv, nullptr, MROWS, 3 * DIM, DIM, 1);

    // 2) Flash attention -> g_attn
    dim3 g2(SEQ / 64, BATCH * HEADS);        // (32, 64)
    flash_attn<<<g2, 128, FLASH_SMEM>>>(flag, attn_ptr);

    // 3) Output projection -> d_out
    dim3 g3(DIM / GBN, MROWS / GBM);         // (8, 64)
    gemm_tf32<<<g3, 256, GEMM_SMEM>>>(attn_ptr, Wout, bout, out, MROWS, DIM, DIM, 2);
}

// round 4
// speedup vs baseline: 3.0961x; 2.7872x over previous
#include <cuda_runtime.h>
#include <cuda_fp16.h>
#include <mma.h>
#include <cstdint>

using namespace nvcuda;

// Problem constants
#define BATCH 4
#define SEQ   2048
#define DIM   1024
#define HEADS 16
#define HDIM  64
#define MROWS (BATCH*SEQ)          // 8192

// ---------------------------------------------------------------------------
// Device-global scratch (no runtime allocation allowed)
// ---------------------------------------------------------------------------
__device__ __half g_xh[(size_t)MROWS * DIM];                       // x fp16
__device__ __half g_wqkvh[(size_t)DIM * 3 * DIM];                  // W_qkv fp16 [1024][3072]
__device__ __half g_wouth[(size_t)DIM * DIM];                      // W_out fp16 [1024][1024]
__device__ __half g_qkv[(size_t)3 * BATCH * HEADS * SEQ * HDIM];   // [which][b][h][s][hd] fp16 (Q pre-scaled)
__device__ __half g_attn[(size_t)MROWS * DIM];                     // [b][s][h*64+hd] fp16

// ---------------------------------------------------------------------------
// cp.async helpers
// ---------------------------------------------------------------------------
__device__ __forceinline__ void cp_async16(void* smem_dst, const void* gmem_src) {
    uint32_t s = (uint32_t)__cvta_generic_to_shared(smem_dst);
    asm volatile("cp.async.cg.shared.global [%0], [%1], 16;\n" :: "r"(s), "l"(gmem_src));
}
#define CP_COMMIT() asm volatile("cp.async.commit_group;\n" ::: "memory")
#define CP_WAIT(n)  asm volatile("cp.async.wait_group %0;\n" :: "n"(n) : "memory")

// ---------------------------------------------------------------------------
// Prep: fp32 -> fp16 elementwise convert (vectorized)
// ---------------------------------------------------------------------------
__global__ void convert_fp16_kernel(const float* __restrict__ src, __half* __restrict__ dst) {
    size_t i = ((size_t)blockIdx.x * blockDim.x + threadIdx.x) * 4;
    float4 v = *reinterpret_cast<const float4*>(src + i);
    *reinterpret_cast<__half2*>(&dst[i])     = __floats2half2_rn(v.x, v.y);
    *reinterpret_cast<__half2*>(&dst[i + 2]) = __floats2half2_rn(v.z, v.w);
}

// ---------------------------------------------------------------------------
// fp16 WMMA GEMM: C[M,N] = A[M,K] @ B[K,N] + bias, K=1024
// BM=128, BN=128, BK=64; 256 threads = 8 warps (4x2 of 32x64 warp tiles).
// Double-buffered cp.async.
// mode 1: A=g_xh, B=g_wqkvh -> scatter fp16 to g_qkv (Q scaled 0.125)
// mode 2: A=g_attn, B=g_wouth -> fp32 to C
// ---------------------------------------------------------------------------
#define GBM 128
#define GBN 128
#define GBK 64
#define LDA 72     // halves (GBK + 8)
#define LDB 136    // halves (GBN + 8)
#define LDC 132    // floats
#define ASZ (GBM * LDA)            // 9216 halves
#define BSZ (GBK * LDB)            // 8704 halves
#define STG (ASZ + BSZ)            // 17920 halves
#define GEMM_SMEM (2 * STG * 2)    // 71680 B (epilogue Csh 128*132*4=67584 fits)

__device__ __forceinline__ void gemm_fill(
    const __half* __restrict__ A, const __half* __restrict__ B,
    __half* As, __half* Bs, int N, int m0, int n0, int k0, int tid)
{
    // A: 128 x 64 halves = 1024 x 16B
    #pragma unroll
    for (int i = 0; i < 4; i++) {
        int idx = tid + i * 256;
        int r = idx >> 3, c = (idx & 7) * 8;
        cp_async16(&As[r * LDA + c], A + (size_t)(m0 + r) * DIM + k0 + c);
    }
    // B: 64 x 128 halves = 1024 x 16B
    #pragma unroll
    for (int i = 0; i < 4; i++) {
        int idx = tid + i * 256;
        int r = idx >> 4, c = (idx & 15) * 8;
        cp_async16(&Bs[r * LDB + c], B + (size_t)(k0 + r) * N + n0 + c);
    }
}

__global__ __launch_bounds__(256, 2) void gemm_h16(
    const float* __restrict__ bias, float* __restrict__ C, int N, int mode)
{
    extern __shared__ __half hsm[];
    __half* Abuf[2] = { hsm, hsm + STG };
    __half* Bbuf[2] = { hsm + ASZ, hsm + STG + ASZ };

    const int tid  = threadIdx.x;
    const int warp = tid >> 5;
    const int wm   = warp & 3;        // 0..3 -> 32-row band
    const int wn   = warp >> 2;       // 0..1 -> 64-col band
    const int m0   = blockIdx.y * GBM;
    const int n0   = blockIdx.x * GBN;

    const __half* A = (mode == 1) ? g_xh : g_attn;
    const __half* B = (mode == 1) ? g_wqkvh : g_wouth;

    wmma::fragment<wmma::accumulator, 16, 16, 16, float> acc[2][4];
    #pragma unroll
    for (int i = 0; i < 2; i++)
        #pragma unroll
        for (int j = 0; j < 4; j++)
            wmma::fill_fragment(acc[i][j], 0.0f);

    const int nk = DIM / GBK;   // 16
    gemm_fill(A, B, Abuf[0], Bbuf[0], N, m0, n0, 0, tid);
    CP_COMMIT();

    for (int t = 0; t < nk; t++) {
        if (t + 1 < nk) {
            gemm_fill(A, B, Abuf[(t + 1) & 1], Bbuf[(t + 1) & 1],
                      N, m0, n0, (t + 1) * GBK, tid);
            CP_COMMIT();
            CP_WAIT(1);
        } else {
            CP_WAIT(0);
        }
        __syncthreads();

        const __half* As = Abuf[t & 1];
        const __half* Bs = Bbuf[t & 1];
        #pragma unroll
        for (int kk = 0; kk < GBK; kk += 16) {
            wmma::fragment<wmma::matrix_a, 16, 16, 16, __half, wmma::row_major> af[2];
            wmma::fragment<wmma::matrix_b, 16, 16, 16, __half, wmma::row_major> bf[4];
            #pragma unroll
            for (int i = 0; i < 2; i++)
                wmma::load_matrix_sync(af[i], &As[(wm * 32 + i * 16) * LDA + kk], LDA);
            #pragma unroll
            for (int j = 0; j < 4; j++)
                wmma::load_matrix_sync(bf[j], &Bs[kk * LDB + wn * 64 + j * 16], LDB);
            #pragma unroll
            for (int i = 0; i < 2; i++)
                #pragma unroll
                for (int j = 0; j < 4; j++)
                    wmma::mma_sync(acc[i][j], af[i], bf[j], acc[i][j]);
        }
        __syncthreads();
    }

    // Epilogue: stage accumulators to shared, add bias, write out.
    float* Csh = reinterpret_cast<float*>(hsm);    // [128][132]
    #pragma unroll
    for (int i = 0; i < 2; i++)
        #pragma unroll
        for (int j = 0; j < 4; j++)
            wmma::store_matrix_sync(&Csh[(wm * 32 + i * 16) * LDC + wn * 64 + j * 16],
                                    acc[i][j], LDC, wmma::mem_row_major);
    __syncthreads();

    if (mode == 1) {
        // 128x128 outputs -> fp16 scatter to g_qkv; 8 halves (16B) per thread-iter
        #pragma unroll
        for (int i = 0; i < 8; i++) {
            int idx = tid + i * 256;           // 2048 chunks of 8
            int r = idx >> 4;                  // row 0..127
            int c = (idx & 15) * 8;            // col 0..120
            int gm = m0 + r;
            int gn = n0 + c;
            const int which = gn >> 10;
            const int d = gn & 1023;
            const int h = d >> 6;
            const int hd = d & 63;
            const float scale = (which == 0) ? 0.125f : 1.0f;
            const int bb = gm >> 11;
            const int ss = gm & 2047;
            union { __half h8[8]; uint4 v; } u;
            #pragma unroll
            for (int e = 0; e < 8; e++) {
                float f = (Csh[r * LDC + c + e] + bias[gn + e]) * scale;
                u.h8[e] = __float2half(f);
            }
            __half* dst = &g_qkv[((((size_t)which * BATCH + bb) * HEADS + h) * SEQ + ss) * HDIM + hd];
            *reinterpret_cast<uint4*>(dst) = u.v;
        }
    } else {
        #pragma unroll
        for (int i = 0; i < 16; i++) {
            int idx = tid + i * 256;           // 4096 float4
            int r = idx >> 5;
            int c = (idx & 31) * 4;
            int gm = m0 + r;
            int gn = n0 + c;
            float4 v = *reinterpret_cast<float4*>(&Csh[r * LDC + c]);
            v.x += bias[gn];
            v.y += bias[gn + 1];
            v.z += bias[gn + 2];
            v.w += bias[gn + 3];
            *reinterpret_cast<float4*>(&C[(size_t)gm * N + gn]) = v;
        }
    }
}

// ---------------------------------------------------------------------------
// Flash attention, fp16 WMMA (16x16x16). One CTA per (q-tile 64, b*h).
// Q pre-scaled by 1/8. 128 threads = 4 warps.
// ---------------------------------------------------------------------------
#define FLDH 72                 // half stride
#define FLDS 68                 // float stride
#define FLASH_SMEM (4 * 64 * FLDH * 2 + 2 * 64 * FLDS * 4 + 128 * 4)

__global__ __launch_bounds__(128) void flash_attn(const int* __restrict__ flag_ptr)
{
    extern __shared__ char smraw[];
    __half* Qs = reinterpret_cast<__half*>(smraw);
    __half* Ks = Qs + 64 * FLDH;
    __half* Vs = Ks + 64 * FLDH;
    __half* Ps = Vs + 64 * FLDH;
    float*  Ss = reinterpret_cast<float*>(Ps + 64 * FLDH);
    float*  Os = Ss + 64 * FLDS;
    float*  mrow = Os + 64 * FLDS;
    float*  lrow = mrow + 64;

    const int qt = blockIdx.x;
    const int bh = blockIdx.y;
    const int b  = bh >> 4;
    const int h  = bh & 15;
    const int tid  = threadIdx.x;
    const int warp = tid >> 5;

    // Load Q tile (fp16, pre-scaled); zero O.
    const __half* qg = g_qkv + ((((size_t)0 * BATCH + b) * HEADS + h) * SEQ + qt * 64) * HDIM;
    #pragma unroll
    for (int i = 0; i < 4; i++) {
        int idx = tid + i * 128;           // 512 chunks of 8 halves
        int r = idx >> 3, c = (idx & 7) * 8;
        *reinterpret_cast<uint4*>(&Qs[r * FLDH + c]) =
            *reinterpret_cast<const uint4*>(qg + r * 64 + c);
    }
    #pragma unroll
    for (int i = 0; i < 8; i++) {
        int idx = tid + i * 128;
        int r = idx >> 4, c = (idx & 15) * 4;
        *reinterpret_cast<float4*>(&Os[r * FLDS + c]) = make_float4(0.f, 0.f, 0.f, 0.f);
    }
    if (tid < 64) { mrow[tid] = -1e30f; lrow[tid] = 0.0f; }
    __syncthreads();

    const int causal = *flag_ptr;
    const int ktmax = causal ? qt : (SEQ / 64 - 1);

    const __half* kgbase = g_qkv + ((((size_t)1 * BATCH + b) * HEADS + h) * SEQ) * HDIM;
    const __half* vgbase = g_qkv + ((((size_t)2 * BATCH + b) * HEADS + h) * SEQ) * HDIM;

    const int srow_r  = tid >> 1;
    const int srow_hf = tid & 1;
    float* srow = &Ss[srow_r * FLDS + srow_hf * 32];
    float* orow = &Os[srow_r * FLDS + srow_hf * 32];
    __half* prow = &Ps[srow_r * FLDH + srow_hf * 32];

    for (int kt = 0; kt <= ktmax; kt++) {
        const __half* kg = kgbase + (size_t)kt * 64 * HDIM;
        const __half* vg = vgbase + (size_t)kt * 64 * HDIM;
        #pragma unroll
        for (int i = 0; i < 4; i++) {
            int idx = tid + i * 128;
            int r = idx >> 3, c = (idx & 7) * 8;
            *reinterpret_cast<uint4*>(&Ks[r * FLDH + c]) =
                *reinterpret_cast<const uint4*>(kg + r * 64 + c);
            *reinterpret_cast<uint4*>(&Vs[r * FLDH + c]) =
                *reinterpret_cast<const uint4*>(vg + r * 64 + c);
        }
        __syncthreads();

        // S = Q @ K^T  (per warp: 16 rows x 64 cols)
        {
            wmma::fragment<wmma::matrix_a, 16, 16, 16, __half, wmma::row_major> af[4];
            #pragma unroll
            for (int d0 = 0; d0 < 4; d0++)
                wmma::load_matrix_sync(af[d0], &Qs[(warp * 16) * FLDH + d0 * 16], FLDH);
            #pragma unroll
            for (int j = 0; j < 4; j++) {
                wmma::fragment<wmma::accumulator, 16, 16, 16, float> sacc;
                wmma::fill_fragment(sacc, 0.0f);
                #pragma unroll
                for (int d0 = 0; d0 < 4; d0++) {
                    wmma::fragment<wmma::matrix_b, 16, 16, 16, __half, wmma::col_major> bf;
                    wmma::load_matrix_sync(bf, &Ks[(j * 16) * FLDH + d0 * 16], FLDH);
                    wmma::mma_sync(sacc, af[d0], bf, sacc);
                }
                wmma::store_matrix_sync(&Ss[(warp * 16) * FLDS + j * 16], sacc,
                                        FLDS, wmma::mem_row_major);
            }
        }
        __syncthreads();

        // Online softmax: 2 threads per row, 32 cols each; P in fp16
        {
            const int nvalid = (causal && kt == qt) ? (srow_r + 1) : 64;
            const int cb = srow_hf * 32;
            const float mold = mrow[srow_r];
            const float lold = lrow[srow_r];

            float4 sv[8];
            float mloc = -1e30f;
            #pragma unroll
            for (int j = 0; j < 8; j++) {
                float4 v = *reinterpret_cast<float4*>(&srow[j * 4]);
                int c0 = cb + j * 4;
                v.x = (c0 + 0 < nvalid) ? v.x : -1e30f;
                v.y = (c0 + 1 < nvalid) ? v.y : -1e30f;
                v.z = (c0 + 2 < nvalid) ? v.z : -1e30f;
                v.w = (c0 + 3 < nvalid) ? v.w : -1e30f;
                sv[j] = v;
                mloc = fmaxf(mloc, fmaxf(fmaxf(v.x, v.y), fmaxf(v.z, v.w)));
            }
            float moth = __shfl_xor_sync(0xffffffffu, mloc, 1);
            float mnew = fmaxf(mold, fmaxf(mloc, moth));

            float sum = 0.0f;
            #pragma unroll
            for (int j = 0; j < 8; j++) {
                float4 v = sv[j];
                v.x = __expf(v.x - mnew);
                v.y = __expf(v.y - mnew);
                v.z = __expf(v.z - mnew);
                v.w = __expf(v.w - mnew);
                sum += (v.x + v.y) + (v.z + v.w);
                *reinterpret_cast<__half2*>(&prow[j * 4])     = __floats2half2_rn(v.x, v.y);
                *reinterpret_cast<__half2*>(&prow[j * 4 + 2]) = __floats2half2_rn(v.z, v.w);
            }
            float soth = __shfl_xor_sync(0xffffffffu, sum, 1);
            sum += soth;

            float alpha = __expf(mold - mnew);
            if (srow_hf == 0) {
                mrow[srow_r] = mnew;
                lrow[srow_r] = lold * alpha + sum;
            }
            #pragma unroll
            for (int j = 0; j < 8; j++) {
                float4 o = *reinterpret_cast<float4*>(&orow[j * 4]);
                o.x *= alpha; o.y *= alpha; o.z *= alpha; o.w *= alpha;
                *reinterpret_cast<float4*>(&orow[j * 4]) = o;
            }
        }
        __syncthreads();

        // O += P @ V
        {
            wmma::fragment<wmma::accumulator, 16, 16, 16, float> oacc[4];
            #pragma unroll
            for (int j = 0; j < 4; j++)
                wmma::load_matrix_sync(oacc[j], &Os[(warp * 16) * FLDS + j * 16],
                                       FLDS, wmma::mem_row_major);
            #pragma unroll
            for (int k0 = 0; k0 < 4; k0++) {
                wmma::fragment<wmma::matrix_a, 16, 16, 16, __half, wmma::row_major> af;
                wmma::load_matrix_sync(af, &Ps[(warp * 16) * FLDH + k0 * 16], FLDH);
                #pragma unroll
                for (int j = 0; j < 4; j++) {
                    wmma::fragment<wmma::matrix_b, 16, 16, 16, __half, wmma::row_major> bf;
                    wmma::load_matrix_sync(bf, &Vs[(k0 * 16) * FLDH + j * 16], FLDH);
                    wmma::mma_sync(oacc[j], af, bf, oacc[j]);
                }
            }
            #pragma unroll
            for (int j = 0; j < 4; j++)
                wmma::store_matrix_sync(&Os[(warp * 16) * FLDS + j * 16], oacc[j],
                                        FLDS, wmma::mem_row_major);
        }
        __syncthreads();
    }

    // Epilogue: O / l -> g_attn fp16
    {
        float inv = 1.0f / lrow[srow_r];
        int sg = qt * 64 + srow_r;
        __half* dst = g_attn + ((size_t)b * SEQ + sg) * DIM + h * HDIM + srow_hf * 32;
        #pragma unroll
        for (int j = 0; j < 8; j++) {
            float4 o = *reinterpret_cast<float4*>(&orow[j * 4]);
            *reinterpret_cast<__half2*>(&dst[j * 4])     = __floats2half2_rn(o.x * inv, o.y * inv);
            *reinterpret_cast<__half2*>(&dst[j * 4 + 2]) = __floats2half2_rn(o.z * inv, o.w * inv);
        }
    }
}

// ---------------------------------------------------------------------------
extern "C" void kernel_launch(void* const* d_in, const int* in_sizes, int n_in,
                              void* d_out, int out_size)
{
    const float* x     = (const float*)d_in[0];
    const float* Wqkv  = (const float*)d_in[1];
    const float* bqkv  = (const float*)d_in[2];
    const float* Wout  = (const float*)d_in[3];
    const float* bout  = (const float*)d_in[4];
    const int*   flag  = (const int*)d_in[5];
    float*       out   = (float*)d_out;

    cudaFuncSetAttribute(gemm_h16, cudaFuncAttributeMaxDynamicSharedMemorySize, GEMM_SMEM);
    cudaFuncSetAttribute(flash_attn, cudaFuncAttributeMaxDynamicSharedMemorySize, FLASH_SMEM);

    __half *xh, *wqkvh, *wouth;
    cudaGetSymbolAddress((void**)&xh, g_xh);
    cudaGetSymbolAddress((void**)&wqkvh, g_wqkvh);
    cudaGetSymbolAddress((void**)&wouth, g_wouth);

    // Prep: fp16 conversions (all elementwise, HBM-bound)
    convert_fp16_kernel<<<(MROWS * DIM) / 1024, 256>>>(x, xh);
    convert_fp16_kernel<<<(DIM * 3 * DIM) / 1024, 256>>>(Wqkv, wqkvh);
    convert_fp16_kernel<<<(DIM * DIM) / 1024, 256>>>(Wout, wouth);

    // 1) QKV projection -> g_qkv fp16 (Q scaled)
    dim3 g1(3 * DIM / GBN, MROWS / GBM);    // (24, 64)
    gemm_h16<<<g1, 256, GEMM_SMEM>>>(bqkv, nullptr, 3 * DIM, 1);

    // 2) Flash attention -> g_attn fp16
    dim3 g2(SEQ / 64, BATCH * HEADS);       // (32, 64)
    flash_attn<<<g2, 128, FLASH_SMEM>>>(flag);

    // 3) Output projection -> d_out fp32
    dim3 g3(DIM / GBN, MROWS / GBM);        // (8, 64)
    gemm_h16<<<g3, 256, GEMM_SMEM>>>(bout, out, DIM, 2);
}

// round 5
// speedup vs baseline: 4.5853x; 1.4810x over previous
#include <cuda_runtime.h>
#include <cuda_fp16.h>
#include <mma.h>
#include <cstdint>

using namespace nvcuda;

// Problem constants
#define BATCH 4
#define SEQ   2048
#define DIM   1024
#define HEADS 16
#define HDIM  64
#define MROWS (BATCH*SEQ)          // 8192

// ---------------------------------------------------------------------------
// Device-global scratch (no runtime allocation allowed)
// ---------------------------------------------------------------------------
__device__ __half g_xh[(size_t)MROWS * DIM];
__device__ __half g_wqkvh[(size_t)DIM * 3 * DIM];
__device__ __half g_wouth[(size_t)DIM * DIM];
__device__ __half g_qkv[(size_t)3 * BATCH * HEADS * SEQ * HDIM];   // [which][b][h][s][hd], Q pre-scaled
__device__ __half g_attn[(size_t)MROWS * DIM];

// ---------------------------------------------------------------------------
// helpers
// ---------------------------------------------------------------------------
__device__ __forceinline__ void cp_async16(void* smem_dst, const void* gmem_src) {
    uint32_t s = (uint32_t)__cvta_generic_to_shared(smem_dst);
    asm volatile("cp.async.cg.shared.global [%0], [%1], 16;\n" :: "r"(s), "l"(gmem_src));
}
#define CP_COMMIT() asm volatile("cp.async.commit_group;\n" ::: "memory")
#define CP_WAIT(n)  asm volatile("cp.async.wait_group %0;\n" :: "n"(n) : "memory")

__device__ __forceinline__ uint32_t smem_addr(const void* p) {
    return (uint32_t)__cvta_generic_to_shared(p);
}
__device__ __forceinline__ void ldsm_x4(uint32_t* r, uint32_t a) {
    asm volatile("ldmatrix.sync.aligned.m8n8.x4.shared.b16 {%0,%1,%2,%3}, [%4];"
                 : "=r"(r[0]), "=r"(r[1]), "=r"(r[2]), "=r"(r[3]) : "r"(a));
}
__device__ __forceinline__ void ldsm_x4_t(uint32_t* r, uint32_t a) {
    asm volatile("ldmatrix.sync.aligned.m8n8.x4.trans.shared.b16 {%0,%1,%2,%3}, [%4];"
                 : "=r"(r[0]), "=r"(r[1]), "=r"(r[2]), "=r"(r[3]) : "r"(a));
}
__device__ __forceinline__ void mma_16816(float* d, const uint32_t* a, const uint32_t* b) {
    asm volatile(
        "mma.sync.aligned.m16n8k16.row.col.f32.f16.f16.f32 "
        "{%0,%1,%2,%3}, {%4,%5,%6,%7}, {%8,%9}, {%0,%1,%2,%3};"
        : "+f"(d[0]), "+f"(d[1]), "+f"(d[2]), "+f"(d[3])
        : "r"(a[0]), "r"(a[1]), "r"(a[2]), "r"(a[3]), "r"(b[0]), "r"(b[1]));
}
__device__ __forceinline__ uint32_t pack_h2(float x, float y) {
    __half2 h = __floats2half2_rn(x, y);
    return *reinterpret_cast<uint32_t*>(&h);
}

// ---------------------------------------------------------------------------
// Prep: fp32 -> fp16 convert
// ---------------------------------------------------------------------------
__global__ void convert_fp16_kernel(const float* __restrict__ src, __half* __restrict__ dst) {
    size_t i = ((size_t)blockIdx.x * blockDim.x + threadIdx.x) * 4;
    float4 v = *reinterpret_cast<const float4*>(src + i);
    *reinterpret_cast<__half2*>(&dst[i])     = __floats2half2_rn(v.x, v.y);
    *reinterpret_cast<__half2*>(&dst[i + 2]) = __floats2half2_rn(v.z, v.w);
}

// ---------------------------------------------------------------------------
// fp16 WMMA GEMM (unchanged from R4): C[M,N] = A[M,1024] @ B[1024,N] + bias
// ---------------------------------------------------------------------------
#define GBM 128
#define GBN 128
#define GBK 64
#define LDA 72
#define LDB 136
#define LDC 132
#define ASZ (GBM * LDA)
#define BSZ (GBK * LDB)
#define STG (ASZ + BSZ)
#define GEMM_SMEM (2 * STG * 2)

__device__ __forceinline__ void gemm_fill(
    const __half* __restrict__ A, const __half* __restrict__ B,
    __half* As, __half* Bs, int N, int m0, int n0, int k0, int tid)
{
    #pragma unroll
    for (int i = 0; i < 4; i++) {
        int idx = tid + i * 256;
        int r = idx >> 3, c = (idx & 7) * 8;
        cp_async16(&As[r * LDA + c], A + (size_t)(m0 + r) * DIM + k0 + c);
    }
    #pragma unroll
    for (int i = 0; i < 4; i++) {
        int idx = tid + i * 256;
        int r = idx >> 4, c = (idx & 15) * 8;
        cp_async16(&Bs[r * LDB + c], B + (size_t)(k0 + r) * N + n0 + c);
    }
}

__global__ __launch_bounds__(256, 2) void gemm_h16(
    const float* __restrict__ bias, float* __restrict__ C, int N, int mode)
{
    extern __shared__ __half hsm[];
    __half* Abuf[2] = { hsm, hsm + STG };
    __half* Bbuf[2] = { hsm + ASZ, hsm + STG + ASZ };

    const int tid  = threadIdx.x;
    const int warp = tid >> 5;
    const int wm   = warp & 3;
    const int wn   = warp >> 2;
    const int m0   = blockIdx.y * GBM;
    const int n0   = blockIdx.x * GBN;

    const __half* A = (mode == 1) ? g_xh : g_attn;
    const __half* B = (mode == 1) ? g_wqkvh : g_wouth;

    wmma::fragment<wmma::accumulator, 16, 16, 16, float> acc[2][4];
    #pragma unroll
    for (int i = 0; i < 2; i++)
        #pragma unroll
        for (int j = 0; j < 4; j++)
            wmma::fill_fragment(acc[i][j], 0.0f);

    const int nk = DIM / GBK;
    gemm_fill(A, B, Abuf[0], Bbuf[0], N, m0, n0, 0, tid);
    CP_COMMIT();

    for (int t = 0; t < nk; t++) {
        if (t + 1 < nk) {
            gemm_fill(A, B, Abuf[(t + 1) & 1], Bbuf[(t + 1) & 1],
                      N, m0, n0, (t + 1) * GBK, tid);
            CP_COMMIT();
            CP_WAIT(1);
        } else {
            CP_WAIT(0);
        }
        __syncthreads();

        const __half* As = Abuf[t & 1];
        const __half* Bs = Bbuf[t & 1];
        #pragma unroll
        for (int kk = 0; kk < GBK; kk += 16) {
            wmma::fragment<wmma::matrix_a, 16, 16, 16, __half, wmma::row_major> af[2];
            wmma::fragment<wmma::matrix_b, 16, 16, 16, __half, wmma::row_major> bf[4];
            #pragma unroll
            for (int i = 0; i < 2; i++)
                wmma::load_matrix_sync(af[i], &As[(wm * 32 + i * 16) * LDA + kk], LDA);
            #pragma unroll
            for (int j = 0; j < 4; j++)
                wmma::load_matrix_sync(bf[j], &Bs[kk * LDB + wn * 64 + j * 16], LDB);
            #pragma unroll
            for (int i = 0; i < 2; i++)
                #pragma unroll
                for (int j = 0; j < 4; j++)
                    wmma::mma_sync(acc[i][j], af[i], bf[j], acc[i][j]);
        }
        __syncthreads();
    }

    float* Csh = reinterpret_cast<float*>(hsm);
    #pragma unroll
    for (int i = 0; i < 2; i++)
        #pragma unroll
        for (int j = 0; j < 4; j++)
            wmma::store_matrix_sync(&Csh[(wm * 32 + i * 16) * LDC + wn * 64 + j * 16],
                                    acc[i][j], LDC, wmma::mem_row_major);
    __syncthreads();

    if (mode == 1) {
        #pragma unroll
        for (int i = 0; i < 8; i++) {
            int idx = tid + i * 256;
            int r = idx >> 4;
            int c = (idx & 15) * 8;
            int gm = m0 + r;
            int gn = n0 + c;
            const int which = gn >> 10;
            const int d = gn & 1023;
            const int h = d >> 6;
            const int hd = d & 63;
            const float scale = (which == 0) ? 0.125f : 1.0f;
            const int bb = gm >> 11;
            const int ss = gm & 2047;
            union { __half h8[8]; uint4 v; } u;
            #pragma unroll
            for (int e = 0; e < 8; e++) {
                float f = (Csh[r * LDC + c + e] + bias[gn + e]) * scale;
                u.h8[e] = __float2half(f);
            }
            __half* dst = &g_qkv[((((size_t)which * BATCH + bb) * HEADS + h) * SEQ + ss) * HDIM + hd];
            *reinterpret_cast<uint4*>(dst) = u.v;
        }
    } else {
        #pragma unroll
        for (int i = 0; i < 16; i++) {
            int idx = tid + i * 256;
            int r = idx >> 5;
            int c = (idx & 31) * 4;
            int gm = m0 + r;
            int gn = n0 + c;
            float4 v = *reinterpret_cast<float4*>(&Csh[r * LDC + c]);
            v.x += bias[gn];
            v.y += bias[gn + 1];
            v.z += bias[gn + 2];
            v.w += bias[gn + 3];
            *reinterpret_cast<float4*>(&C[(size_t)gm * N + gn]) = v;
        }
    }
}

// ---------------------------------------------------------------------------
// Register-resident FA2 flash attention. mma.sync m16n8k16 + ldmatrix.
// CTA: 128 thr = 4 warps; q-tile 64 (16 rows/warp); kv-tile 64.
// S, P, O all in registers; K/V double-buffered cp.async.
// ---------------------------------------------------------------------------
#define FST 72   // smem stride in halves

__global__ __launch_bounds__(128) void flash_attn(const int* __restrict__ flag_ptr)
{
    __shared__ __half Qs[64 * FST];
    __shared__ __half Ks[2][64 * FST];
    __shared__ __half Vs[2][64 * FST];

    const int qt = blockIdx.x;
    const int bh = blockIdx.y;
    const int b  = bh >> 4;
    const int h  = bh & 15;
    const int tid  = threadIdx.x;
    const int w    = tid >> 5;
    const int lane = tid & 31;
    const int g    = lane >> 2;     // row group 0..7
    const int t4   = lane & 3;      // col pair 0..3
    const int sub  = lane >> 3;     // ldmatrix sub-matrix 0..3
    const int rr   = lane & 7;      // ldmatrix row 0..7

    // ---- Load Q tile (fp16, pre-scaled by 1/8) into smem ----
    const __half* qg = g_qkv + ((((size_t)0 * BATCH + b) * HEADS + h) * SEQ + qt * 64) * HDIM;
    #pragma unroll
    for (int i = 0; i < 4; i++) {
        int idx = tid + i * 128;
        int r = idx >> 3, c = (idx & 7) * 8;
        *reinterpret_cast<uint4*>(&Qs[r * FST + c]) =
            *reinterpret_cast<const uint4*>(qg + r * 64 + c);
    }
    __syncthreads();

    // ---- Q A-fragments (persistent in registers) ----
    uint32_t QA[4][4];
    #pragma unroll
    for (int c = 0; c < 4; c++) {
        uint32_t a = smem_addr(&Qs[(w * 16 + (sub & 1) * 8 + rr) * FST + c * 16 + (sub >> 1) * 8]);
        ldsm_x4(QA[c], a);
    }

    // ---- State ----
    float O[8][4];
    #pragma unroll
    for (int j = 0; j < 8; j++)
        #pragma unroll
        for (int e = 0; e < 4; e++) O[j][e] = 0.0f;
    float m0 = -1e30f, m1 = -1e30f, l0 = 0.0f, l1 = 0.0f;

    const int causal = *flag_ptr;
    const int ktmax = causal ? qt : (SEQ / 64 - 1);
    const int qrow0 = qt * 64 + w * 16 + g;
    const int qrow1 = qrow0 + 8;

    const __half* kgbase = g_qkv + ((((size_t)1 * BATCH + b) * HEADS + h) * SEQ) * HDIM;
    const __half* vgbase = g_qkv + ((((size_t)2 * BATCH + b) * HEADS + h) * SEQ) * HDIM;

    // ---- Prefetch kt = 0 ----
    {
        const __half* kg = kgbase;
        const __half* vg = vgbase;
        #pragma unroll
        for (int i = 0; i < 4; i++) {
            int idx = tid + i * 128;
            int r = idx >> 3, c = (idx & 7) * 8;
            cp_async16(&Ks[0][r * FST + c], kg + r * 64 + c);
            cp_async16(&Vs[0][r * FST + c], vg + r * 64 + c);
        }
        CP_COMMIT();
    }

    for (int kt = 0; kt <= ktmax; kt++) {
        if (kt + 1 <= ktmax) {
            const __half* kg = kgbase + (size_t)(kt + 1) * 64 * HDIM;
            const __half* vg = vgbase + (size_t)(kt + 1) * 64 * HDIM;
            int nb = (kt + 1) & 1;
            #pragma unroll
            for (int i = 0; i < 4; i++) {
                int idx = tid + i * 128;
                int r = idx >> 3, c = (idx & 7) * 8;
                cp_async16(&Ks[nb][r * FST + c], kg + r * 64 + c);
                cp_async16(&Vs[nb][r * FST + c], vg + r * 64 + c);
            }
            CP_COMMIT();
            CP_WAIT(1);
        } else {
            CP_WAIT(0);
        }
        __syncthreads();

        const __half* Kb = Ks[kt & 1];
        const __half* Vb = Vs[kt & 1];

        // ---- S = Q @ K^T  (registers) ----
        float S[8][4];
        #pragma unroll
        for (int j = 0; j < 8; j++)
            #pragma unroll
            for (int e = 0; e < 4; e++) S[j][e] = 0.0f;

        #pragma unroll
        for (int p = 0; p < 4; p++) {        // n-tile pairs (cols 16p..16p+15)
            #pragma unroll
            for (int c = 0; c < 4; c++) {    // k chunks (hd 16c..)
                uint32_t Bf[4];
                uint32_t a = smem_addr(&Kb[((2 * p + (sub >> 1)) * 8 + rr) * FST
                                           + c * 16 + (sub & 1) * 8]);
                ldsm_x4(Bf, a);
                mma_16816(S[2 * p],     QA[c], &Bf[0]);
                mma_16816(S[2 * p + 1], QA[c], &Bf[2]);
            }
        }

        // ---- Causal mask (diagonal tile only) ----
        if (causal && kt == qt) {
            #pragma unroll
            for (int j = 0; j < 8; j++) {
                int col = kt * 64 + j * 8 + 2 * t4;
                if (col > qrow0)     S[j][0] = -1e30f;
                if (col + 1 > qrow0) S[j][1] = -1e30f;
                if (col > qrow1)     S[j][2] = -1e30f;
                if (col + 1 > qrow1) S[j][3] = -1e30f;
            }
        }

        // ---- Online softmax (register + quad shuffles) ----
        float mx0 = -1e30f, mx1 = -1e30f;
        #pragma unroll
        for (int j = 0; j < 8; j++) {
            mx0 = fmaxf(mx0, fmaxf(S[j][0], S[j][1]));
            mx1 = fmaxf(mx1, fmaxf(S[j][2], S[j][3]));
        }
        mx0 = fmaxf(mx0, __shfl_xor_sync(0xffffffffu, mx0, 1));
        mx0 = fmaxf(mx0, __shfl_xor_sync(0xffffffffu, mx0, 2));
        mx1 = fmaxf(mx1, __shfl_xor_sync(0xffffffffu, mx1, 1));
        mx1 = fmaxf(mx1, __shfl_xor_sync(0xffffffffu, mx1, 2));

        float mn0 = fmaxf(m0, mx0);
        float mn1 = fmaxf(m1, mx1);
        float a0 = __expf(m0 - mn0);
        float a1 = __expf(m1 - mn1);

        float s0 = 0.0f, s1 = 0.0f;
        #pragma unroll
        for (int j = 0; j < 8; j++) {
            S[j][0] = __expf(S[j][0] - mn0);
            S[j][1] = __expf(S[j][1] - mn0);
            S[j][2] = __expf(S[j][2] - mn1);
            S[j][3] = __expf(S[j][3] - mn1);
            s0 += S[j][0] + S[j][1];
            s1 += S[j][2] + S[j][3];
        }
        s0 += __shfl_xor_sync(0xffffffffu, s0, 1);
        s0 += __shfl_xor_sync(0xffffffffu, s0, 2);
        s1 += __shfl_xor_sync(0xffffffffu, s1, 1);
        s1 += __shfl_xor_sync(0xffffffffu, s1, 2);

        l0 = l0 * a0 + s0;
        l1 = l1 * a1 + s1;
        m0 = mn0; m1 = mn1;

        #pragma unroll
        for (int j = 0; j < 8; j++) {
            O[j][0] *= a0; O[j][1] *= a0;
            O[j][2] *= a1; O[j][3] *= a1;
        }

        // ---- O += P @ V  (P = S fragments repacked fp16 in registers) ----
        #pragma unroll
        for (int c = 0; c < 4; c++) {        // k chunks over s-dim (16 each)
            uint32_t PA[4];
            PA[0] = pack_h2(S[2 * c][0],     S[2 * c][1]);
            PA[1] = pack_h2(S[2 * c][2],     S[2 * c][3]);
            PA[2] = pack_h2(S[2 * c + 1][0], S[2 * c + 1][1]);
            PA[3] = pack_h2(S[2 * c + 1][2], S[2 * c + 1][3]);
            #pragma unroll
            for (int jj = 0; jj < 8; jj += 2) {   // hd n-tile pairs
                uint32_t Bf[4];
                uint32_t a = smem_addr(&Vb[(c * 16 + (sub & 1) * 8 + rr) * FST
                                           + (jj + (sub >> 1)) * 8]);
                ldsm_x4_t(Bf, a);
                mma_16816(O[jj],     PA, &Bf[0]);
                mma_16816(O[jj + 1], PA, &Bf[2]);
            }
        }
        __syncthreads();
    }

    // ---- Epilogue: O / l -> g_attn fp16 ----
    {
        float inv0 = 1.0f / l0;
        float inv1 = 1.0f / l1;
        __half* d0 = g_attn + ((size_t)b * SEQ + qrow0) * DIM + h * HDIM;
        __half* d1 = g_attn + ((size_t)b * SEQ + qrow1) * DIM + h * HDIM;
        #pragma unroll
        for (int j = 0; j < 8; j++) {
            int hd = j * 8 + 2 * t4;
            *reinterpret_cast<uint32_t*>(d0 + hd) = pack_h2(O[j][0] * inv0, O[j][1] * inv0);
            *reinterpret_cast<uint32_t*>(d1 + hd) = pack_h2(O[j][2] * inv1, O[j][3] * inv1);
        }
    }
}

// ---------------------------------------------------------------------------
extern "C" void kernel_launch(void* const* d_in, const int* in_sizes, int n_in,
                              void* d_out, int out_size)
{
    const float* x     = (const float*)d_in[0];
    const float* Wqkv  = (const float*)d_in[1];
    const float* bqkv  = (const float*)d_in[2];
    const float* Wout  = (const float*)d_in[3];
    const float* bout  = (const float*)d_in[4];
    const int*   flag  = (const int*)d_in[5];
    float*       out   = (float*)d_out;

    cudaFuncSetAttribute(gemm_h16, cudaFuncAttributeMaxDynamicSharedMemorySize, GEMM_SMEM);

    __half *xh, *wqkvh, *wouth;
    cudaGetSymbolAddress((void**)&xh, g_xh);
    cudaGetSymbolAddress((void**)&wqkvh, g_wqkvh);
    cudaGetSymbolAddress((void**)&wouth, g_wouth);

    convert_fp16_kernel<<<(MROWS * DIM) / 1024, 256>>>(x, xh);
    convert_fp16_kernel<<<(DIM * 3 * DIM) / 1024, 256>>>(Wqkv, wqkvh);
    convert_fp16_kernel<<<(DIM * DIM) / 1024, 256>>>(Wout, wouth);

    dim3 g1(3 * DIM / GBN, MROWS / GBM);
    gemm_h16<<<g1, 256, GEMM_SMEM>>>(bqkv, nullptr, 3 * DIM, 1);

    dim3 g2(SEQ / 64, BATCH * HEADS);
    flash_attn<<<g2, 128>>>(flag);

    dim3 g3(DIM / GBN, MROWS / GBM);
    gemm_h16<<<g3, 256, GEMM_SMEM>>>(bout, out, DIM, 2);
}

// round 6
// speedup vs baseline: 6.0271x; 1.3144x over previous
#include <cuda_runtime.h>
#include <cuda_fp16.h>
#include <cstdint>

// Problem constants
#define BATCH 4
#define SEQ   2048
#define DIM   1024
#define HEADS 16
#define HDIM  64
#define MROWS (BATCH*SEQ)          // 8192

// ---------------------------------------------------------------------------
// Device-global scratch (no runtime allocation allowed)
// ---------------------------------------------------------------------------
__device__ __half g_xh[(size_t)MROWS * DIM];
__device__ __half g_wqkvh[(size_t)DIM * 3 * DIM];
__device__ __half g_wouth[(size_t)DIM * DIM];
__device__ __half g_qkv[(size_t)3 * BATCH * HEADS * SEQ * HDIM];   // [which][b][h][s][hd], Q pre-scaled
__device__ __half g_attn[(size_t)MROWS * DIM];

// ---------------------------------------------------------------------------
// helpers
// ---------------------------------------------------------------------------
__device__ __forceinline__ void cp_async16(void* smem_dst, const void* gmem_src) {
    uint32_t s = (uint32_t)__cvta_generic_to_shared(smem_dst);
    asm volatile("cp.async.cg.shared.global [%0], [%1], 16;\n" :: "r"(s), "l"(gmem_src));
}
#define CP_COMMIT() asm volatile("cp.async.commit_group;\n" ::: "memory")
#define CP_WAIT(n)  asm volatile("cp.async.wait_group %0;\n" :: "n"(n) : "memory")

__device__ __forceinline__ uint32_t smem_addr(const void* p) {
    return (uint32_t)__cvta_generic_to_shared(p);
}
__device__ __forceinline__ void ldsm_x4(uint32_t* r, uint32_t a) {
    asm volatile("ldmatrix.sync.aligned.m8n8.x4.shared.b16 {%0,%1,%2,%3}, [%4];"
                 : "=r"(r[0]), "=r"(r[1]), "=r"(r[2]), "=r"(r[3]) : "r"(a));
}
__device__ __forceinline__ void ldsm_x4_t(uint32_t* r, uint32_t a) {
    asm volatile("ldmatrix.sync.aligned.m8n8.x4.trans.shared.b16 {%0,%1,%2,%3}, [%4];"
                 : "=r"(r[0]), "=r"(r[1]), "=r"(r[2]), "=r"(r[3]) : "r"(a));
}
__device__ __forceinline__ void mma_16816(float* d, const uint32_t* a, const uint32_t* b) {
    asm volatile(
        "mma.sync.aligned.m16n8k16.row.col.f32.f16.f16.f32 "
        "{%0,%1,%2,%3}, {%4,%5,%6,%7}, {%8,%9}, {%0,%1,%2,%3};"
        : "+f"(d[0]), "+f"(d[1]), "+f"(d[2]), "+f"(d[3])
        : "r"(a[0]), "r"(a[1]), "r"(a[2]), "r"(a[3]), "r"(b[0]), "r"(b[1]));
}
__device__ __forceinline__ uint32_t pack_h2(float x, float y) {
    __half2 h = __floats2half2_rn(x, y);
    return *reinterpret_cast<uint32_t*>(&h);
}

// ---------------------------------------------------------------------------
// Prep: fp32 -> fp16 convert
// ---------------------------------------------------------------------------
__global__ void convert_fp16_kernel(const float* __restrict__ src, __half* __restrict__ dst) {
    size_t i = ((size_t)blockIdx.x * blockDim.x + threadIdx.x) * 4;
    float4 v = *reinterpret_cast<const float4*>(src + i);
    *reinterpret_cast<__half2*>(&dst[i])     = __floats2half2_rn(v.x, v.y);
    *reinterpret_cast<__half2*>(&dst[i + 2]) = __floats2half2_rn(v.z, v.w);
}

// ---------------------------------------------------------------------------
// Raw mma.sync GEMM: C[M,N] = A[M,1024] @ B[1024,N] + bias
// CTA tile 128x128, BK=64, 3-stage cp.async pipeline, 8 warps (warp: 32x64).
// mode 1: A=g_xh, B=g_wqkvh -> fp16 scatter to g_qkv (Q scaled 0.125)
// mode 2: A=g_attn, B=g_wouth -> fp32 to C
// ---------------------------------------------------------------------------
#define GBK 64
#define LDA 72      // halves (144B rows: conflict-free ldmatrix)
#define LDB 136     // halves (272B rows)
#define ASTG (128 * LDA)   // 9216 halves per stage
#define BSTG (GBK * LDB)   // 8704 halves per stage
#define GEMM_SMEM ((3 * (ASTG + BSTG)) * 2)   // 107520 B -> 2 CTAs/SM

__device__ __forceinline__ void gemm_fill(
    const __half* __restrict__ A, const __half* __restrict__ B,
    __half* As, __half* Bs, int N, int m0, int n0, int k0, int tid)
{
    #pragma unroll
    for (int i = 0; i < 4; i++) {
        int idx = tid + i * 256;
        int r = idx >> 3, c = (idx & 7) * 8;
        cp_async16(&As[r * LDA + c], A + (size_t)(m0 + r) * DIM + k0 + c);
    }
    #pragma unroll
    for (int i = 0; i < 4; i++) {
        int idx = tid + i * 256;
        int r = idx >> 4, c = (idx & 15) * 8;
        cp_async16(&Bs[r * LDB + c], B + (size_t)(k0 + r) * N + n0 + c);
    }
}

__global__ __launch_bounds__(256, 2) void gemm_h16(
    const float* __restrict__ bias, float* __restrict__ C, int N, int mode)
{
    extern __shared__ __half hsm[];
    __half* Asm = hsm;                 // [3][ASTG]
    __half* Bsm = hsm + 3 * ASTG;      // [3][BSTG]

    const int tid  = threadIdx.x;
    const int warp = tid >> 5;
    const int lane = tid & 31;
    const int wm   = warp & 3;         // 32-row band
    const int wn   = warp >> 2;        // 64-col band
    const int g    = lane >> 2;
    const int t4   = lane & 3;
    const int sub  = lane >> 3;
    const int rr   = lane & 7;
    const int m0   = blockIdx.y * 128;
    const int n0   = blockIdx.x * 128;

    const __half* A = (mode == 1) ? g_xh : g_attn;
    const __half* B = (mode == 1) ? g_wqkvh : g_wouth;

    float acc[2][8][4];
    #pragma unroll
    for (int mt = 0; mt < 2; mt++)
        #pragma unroll
        for (int nt = 0; nt < 8; nt++)
            #pragma unroll
            for (int e = 0; e < 4; e++) acc[mt][nt][e] = 0.0f;

    const int nk = DIM / GBK;   // 16
    gemm_fill(A, B, Asm, Bsm, N, m0, n0, 0, tid);
    CP_COMMIT();
    gemm_fill(A, B, Asm + ASTG, Bsm + BSTG, N, m0, n0, GBK, tid);
    CP_COMMIT();

    for (int t = 0; t < nk; t++) {
        if (t < nk - 2) { CP_WAIT(1); } else { CP_WAIT(0); }
        __syncthreads();
        if (t + 2 < nk) {
            int st = (t + 2) % 3;
            gemm_fill(A, B, Asm + st * ASTG, Bsm + st * BSTG, N, m0, n0, (t + 2) * GBK, tid);
            CP_COMMIT();
        }

        const __half* As = Asm + (t % 3) * ASTG;
        const __half* Bs = Bsm + (t % 3) * BSTG;

        #pragma unroll
        for (int ks = 0; ks < 4; ks++) {
            uint32_t Af[2][4];
            #pragma unroll
            for (int mt = 0; mt < 2; mt++) {
                uint32_t a = smem_addr(&As[(wm * 32 + mt * 16 + (sub & 1) * 8 + rr) * LDA
                                           + ks * 16 + (sub >> 1) * 8]);
                ldsm_x4(Af[mt], a);
            }
            uint32_t Bf[4][4];
            #pragma unroll
            for (int p = 0; p < 4; p++) {
                uint32_t a = smem_addr(&Bs[(ks * 16 + (sub & 1) * 8 + rr) * LDB
                                           + wn * 64 + p * 16 + (sub >> 1) * 8]);
                ldsm_x4_t(Bf[p], a);
            }
            #pragma unroll
            for (int mt = 0; mt < 2; mt++)
                #pragma unroll
                for (int p = 0; p < 4; p++) {
                    mma_16816(acc[mt][2 * p],     Af[mt], &Bf[p][0]);
                    mma_16816(acc[mt][2 * p + 1], Af[mt], &Bf[p][2]);
                }
        }
    }

    // ---- Direct register epilogue ----
    if (mode == 1) {
        #pragma unroll
        for (int nt = 0; nt < 8; nt++) {
            const int gn = n0 + wn * 64 + nt * 8 + 2 * t4;
            const int which = gn >> 10;
            const int d = gn & 1023;
            const int h = d >> 6;
            const int hd = d & 63;
            const float scale = (which == 0) ? 0.125f : 1.0f;
            const float b0 = bias[gn] * scale;
            const float b1 = bias[gn + 1] * scale;
            __half* base = &g_qkv[(((size_t)which * BATCH) * HEADS) * SEQ * HDIM];
            #pragma unroll
            for (int mt = 0; mt < 2; mt++) {
                int r0 = m0 + wm * 32 + mt * 16 + g;
                int bb = r0 >> 11;
                int ss = r0 & 2047;
                __half* d0 = &g_qkv[((((size_t)which * BATCH + bb) * HEADS + h) * SEQ + ss) * HDIM + hd];
                __half* d1 = &g_qkv[((((size_t)which * BATCH + bb) * HEADS + h) * SEQ + ss + 8) * HDIM + hd];
                *reinterpret_cast<uint32_t*>(d0) =
                    pack_h2(acc[mt][nt][0] * scale + b0, acc[mt][nt][1] * scale + b1);
                *reinterpret_cast<uint32_t*>(d1) =
                    pack_h2(acc[mt][nt][2] * scale + b0, acc[mt][nt][3] * scale + b1);
            }
            (void)base;
        }
    } else {
        #pragma unroll
        for (int nt = 0; nt < 8; nt++) {
            const int gn = n0 + wn * 64 + nt * 8 + 2 * t4;
            const float b0 = bias[gn];
            const float b1 = bias[gn + 1];
            #pragma unroll
            for (int mt = 0; mt < 2; mt++) {
                int r0 = m0 + wm * 32 + mt * 16 + g;
                float2 v0 = { acc[mt][nt][0] + b0, acc[mt][nt][1] + b1 };
                float2 v1 = { acc[mt][nt][2] + b0, acc[mt][nt][3] + b1 };
                *reinterpret_cast<float2*>(&C[(size_t)r0 * N + gn]) = v0;
                *reinterpret_cast<float2*>(&C[(size_t)(r0 + 8) * N + gn]) = v1;
            }
        }
    }
}

// ---------------------------------------------------------------------------
// Register-resident FA2 flash attention (unchanged from R5).
// ---------------------------------------------------------------------------
#define FST 72   // smem stride in halves

__global__ __launch_bounds__(128) void flash_attn(const int* __restrict__ flag_ptr)
{
    __shared__ __half Qs[64 * FST];
    __shared__ __half Ks[2][64 * FST];
    __shared__ __half Vs[2][64 * FST];

    const int qt = blockIdx.x;
    const int bh = blockIdx.y;
    const int b  = bh >> 4;
    const int h  = bh & 15;
    const int tid  = threadIdx.x;
    const int w    = tid >> 5;
    const int lane = tid & 31;
    const int g    = lane >> 2;
    const int t4   = lane & 3;
    const int sub  = lane >> 3;
    const int rr   = lane & 7;

    const __half* qg = g_qkv + ((((size_t)0 * BATCH + b) * HEADS + h) * SEQ + qt * 64) * HDIM;
    #pragma unroll
    for (int i = 0; i < 4; i++) {
        int idx = tid + i * 128;
        int r = idx >> 3, c = (idx & 7) * 8;
        *reinterpret_cast<uint4*>(&Qs[r * FST + c]) =
            *reinterpret_cast<const uint4*>(qg + r * 64 + c);
    }
    __syncthreads();

    uint32_t QA[4][4];
    #pragma unroll
    for (int c = 0; c < 4; c++) {
        uint32_t a = smem_addr(&Qs[(w * 16 + (sub & 1) * 8 + rr) * FST + c * 16 + (sub >> 1) * 8]);
        ldsm_x4(QA[c], a);
    }

    float O[8][4];
    #pragma unroll
    for (int j = 0; j < 8; j++)
        #pragma unroll
        for (int e = 0; e < 4; e++) O[j][e] = 0.0f;
    float m0 = -1e30f, m1 = -1e30f, l0 = 0.0f, l1 = 0.0f;

    const int causal = *flag_ptr;
    const int ktmax = causal ? qt : (SEQ / 64 - 1);
    const int qrow0 = qt * 64 + w * 16 + g;
    const int qrow1 = qrow0 + 8;

    const __half* kgbase = g_qkv + ((((size_t)1 * BATCH + b) * HEADS + h) * SEQ) * HDIM;
    const __half* vgbase = g_qkv + ((((size_t)2 * BATCH + b) * HEADS + h) * SEQ) * HDIM;

    {
        #pragma unroll
        for (int i = 0; i < 4; i++) {
            int idx = tid + i * 128;
            int r = idx >> 3, c = (idx & 7) * 8;
            cp_async16(&Ks[0][r * FST + c], kgbase + r * 64 + c);
            cp_async16(&Vs[0][r * FST + c], vgbase + r * 64 + c);
        }
        CP_COMMIT();
    }

    for (int kt = 0; kt <= ktmax; kt++) {
        if (kt + 1 <= ktmax) {
            const __half* kg = kgbase + (size_t)(kt + 1) * 64 * HDIM;
            const __half* vg = vgbase + (size_t)(kt + 1) * 64 * HDIM;
            int nb = (kt + 1) & 1;
            #pragma unroll
            for (int i = 0; i < 4; i++) {
                int idx = tid + i * 128;
                int r = idx >> 3, c = (idx & 7) * 8;
                cp_async16(&Ks[nb][r * FST + c], kg + r * 64 + c);
                cp_async16(&Vs[nb][r * FST + c], vg + r * 64 + c);
            }
            CP_COMMIT();
            CP_WAIT(1);
        } else {
            CP_WAIT(0);
        }
        __syncthreads();

        const __half* Kb = Ks[kt & 1];
        const __half* Vb = Vs[kt & 1];

        float S[8][4];
        #pragma unroll
        for (int j = 0; j < 8; j++)
            #pragma unroll
            for (int e = 0; e < 4; e++) S[j][e] = 0.0f;

        #pragma unroll
        for (int p = 0; p < 4; p++) {
            #pragma unroll
            for (int c = 0; c < 4; c++) {
                uint32_t Bf[4];
                uint32_t a = smem_addr(&Kb[((2 * p + (sub >> 1)) * 8 + rr) * FST
                                           + c * 16 + (sub & 1) * 8]);
                ldsm_x4(Bf, a);
                mma_16816(S[2 * p],     QA[c], &Bf[0]);
                mma_16816(S[2 * p + 1], QA[c], &Bf[2]);
            }
        }

        if (causal && kt == qt) {
            #pragma unroll
            for (int j = 0; j < 8; j++) {
                int col = kt * 64 + j * 8 + 2 * t4;
                if (col > qrow0)     S[j][0] = -1e30f;
                if (col + 1 > qrow0) S[j][1] = -1e30f;
                if (col > qrow1)     S[j][2] = -1e30f;
                if (col + 1 > qrow1) S[j][3] = -1e30f;
            }
        }

        float mx0 = -1e30f, mx1 = -1e30f;
        #pragma unroll
        for (int j = 0; j < 8; j++) {
            mx0 = fmaxf(mx0, fmaxf(S[j][0], S[j][1]));
            mx1 = fmaxf(mx1, fmaxf(S[j][2], S[j][3]));
        }
        mx0 = fmaxf(mx0, __shfl_xor_sync(0xffffffffu, mx0, 1));
        mx0 = fmaxf(mx0, __shfl_xor_sync(0xffffffffu, mx0, 2));
        mx1 = fmaxf(mx1, __shfl_xor_sync(0xffffffffu, mx1, 1));
        mx1 = fmaxf(mx1, __shfl_xor_sync(0xffffffffu, mx1, 2));

        float mn0 = fmaxf(m0, mx0);
        float mn1 = fmaxf(m1, mx1);
        float a0 = __expf(m0 - mn0);
        float a1 = __expf(m1 - mn1);

        float s0 = 0.0f, s1 = 0.0f;
        #pragma unroll
        for (int j = 0; j < 8; j++) {
            S[j][0] = __expf(S[j][0] - mn0);
            S[j][1] = __expf(S[j][1] - mn0);
            S[j][2] = __expf(S[j][2] - mn1);
            S[j][3] = __expf(S[j][3] - mn1);
            s0 += S[j][0] + S[j][1];
            s1 += S[j][2] + S[j][3];
        }
        s0 += __shfl_xor_sync(0xffffffffu, s0, 1);
        s0 += __shfl_xor_sync(0xffffffffu, s0, 2);
        s1 += __shfl_xor_sync(0xffffffffu, s1, 1);
        s1 += __shfl_xor_sync(0xffffffffu, s1, 2);

        l0 = l0 * a0 + s0;
        l1 = l1 * a1 + s1;
        m0 = mn0; m1 = mn1;

        #pragma unroll
        for (int j = 0; j < 8; j++) {
            O[j][0] *= a0; O[j][1] *= a0;
            O[j][2] *= a1; O[j][3] *= a1;
        }

        #pragma unroll
        for (int c = 0; c < 4; c++) {
            uint32_t PA[4];
            PA[0] = pack_h2(S[2 * c][0],     S[2 * c][1]);
            PA[1] = pack_h2(S[2 * c][2],     S[2 * c][3]);
            PA[2] = pack_h2(S[2 * c + 1][0], S[2 * c + 1][1]);
            PA[3] = pack_h2(S[2 * c + 1][2], S[2 * c + 1][3]);
            #pragma unroll
            for (int jj = 0; jj < 8; jj += 2) {
                uint32_t Bf[4];
                uint32_t a = smem_addr(&Vb[(c * 16 + (sub & 1) * 8 + rr) * FST
                                           + (jj + (sub >> 1)) * 8]);
                ldsm_x4_t(Bf, a);
                mma_16816(O[jj],     PA, &Bf[0]);
                mma_16816(O[jj + 1], PA, &Bf[2]);
            }
        }
        __syncthreads();
    }

    {
        float inv0 = 1.0f / l0;
        float inv1 = 1.0f / l1;
        __half* d0 = g_attn + ((size_t)b * SEQ + qrow0) * DIM + h * HDIM;
        __half* d1 = g_attn + ((size_t)b * SEQ + qrow1) * DIM + h * HDIM;
        #pragma unroll
        for (int j = 0; j < 8; j++) {
            int hd = j * 8 + 2 * t4;
            *reinterpret_cast<uint32_t*>(d0 + hd) = pack_h2(O[j][0] * inv0, O[j][1] * inv0);
            *reinterpret_cast<uint32_t*>(d1 + hd) = pack_h2(O[j][2] * inv1, O[j][3] * inv1);
        }
    }
}

// ---------------------------------------------------------------------------
extern "C" void kernel_launch(void* const* d_in, const int* in_sizes, int n_in,
                              void* d_out, int out_size)
{
    const float* x     = (const float*)d_in[0];
    const float* Wqkv  = (const float*)d_in[1];
    const float* bqkv  = (const float*)d_in[2];
    const float* Wout  = (const float*)d_in[3];
    const float* bout  = (const float*)d_in[4];
    const int*   flag  = (const int*)d_in[5];
    float*       out   = (float*)d_out;

    cudaFuncSetAttribute(gemm_h16, cudaFuncAttributeMaxDynamicSharedMemorySize, GEMM_SMEM);

    __half *xh, *wqkvh, *wouth;
    cudaGetSymbolAddress((void**)&xh, g_xh);
    cudaGetSymbolAddress((void**)&wqkvh, g_wqkvh);
    cudaGetSymbolAddress((void**)&wouth, g_wouth);

    convert_fp16_kernel<<<(MROWS * DIM) / 1024, 256>>>(x, xh);
    convert_fp16_kernel<<<(DIM * 3 * DIM) / 1024, 256>>>(Wqkv, wqkvh);
    convert_fp16_kernel<<<(DIM * DIM) / 1024, 256>>>(Wout, wouth);

    dim3 g1(3 * DIM / 128, MROWS / 128);   // (24, 64)
    gemm_h16<<<g1, 256, GEMM_SMEM>>>(bqkv, nullptr, 3 * DIM, 1);

    dim3 g2(SEQ / 64, BATCH * HEADS);      // (32, 64)
    flash_attn<<<g2, 128>>>(flag);

    dim3 g3(DIM / 128, MROWS / 128);       // (8, 64)
    gemm_h16<<<g3, 256, GEMM_SMEM>>>(bout, out, DIM, 2);
}

// round 7
// speedup vs baseline: 6.1053x; 1.0130x over previous
#include <cuda_runtime.h>
#include <cuda_fp16.h>
#include <cstdint>

// Problem constants
#define BATCH 4
#define SEQ   2048
#define DIM   1024
#define HEADS 16
#define HDIM  64
#define MROWS (BATCH*SEQ)          // 8192

// ---------------------------------------------------------------------------
// Device-global scratch (no runtime allocation allowed)
// ---------------------------------------------------------------------------
__device__ __half g_xh[(size_t)MROWS * DIM];
__device__ __half g_wqkvh[(size_t)DIM * 3 * DIM];
__device__ __half g_wouth[(size_t)DIM * DIM];
__device__ __half g_qkv[(size_t)3 * BATCH * HEADS * SEQ * HDIM];   // [which][b][h][s][hd], Q pre-scaled
__device__ __half g_attn[(size_t)MROWS * DIM];

// ---------------------------------------------------------------------------
// helpers
// ---------------------------------------------------------------------------
__device__ __forceinline__ void cp_async16(void* smem_dst, const void* gmem_src) {
    uint32_t s = (uint32_t)__cvta_generic_to_shared(smem_dst);
    asm volatile("cp.async.cg.shared.global [%0], [%1], 16;\n" :: "r"(s), "l"(gmem_src));
}
#define CP_COMMIT() asm volatile("cp.async.commit_group;\n" ::: "memory")
#define CP_WAIT(n)  asm volatile("cp.async.wait_group %0;\n" :: "n"(n) : "memory")

__device__ __forceinline__ uint32_t smem_addr(const void* p) {
    return (uint32_t)__cvta_generic_to_shared(p);
}
__device__ __forceinline__ void ldsm_x4(uint32_t* r, uint32_t a) {
    asm volatile("ldmatrix.sync.aligned.m8n8.x4.shared.b16 {%0,%1,%2,%3}, [%4];"
                 : "=r"(r[0]), "=r"(r[1]), "=r"(r[2]), "=r"(r[3]) : "r"(a));
}
__device__ __forceinline__ void ldsm_x4_t(uint32_t* r, uint32_t a) {
    asm volatile("ldmatrix.sync.aligned.m8n8.x4.trans.shared.b16 {%0,%1,%2,%3}, [%4];"
                 : "=r"(r[0]), "=r"(r[1]), "=r"(r[2]), "=r"(r[3]) : "r"(a));
}
__device__ __forceinline__ void mma_16816(float* d, const uint32_t* a, const uint32_t* b) {
    asm volatile(
        "mma.sync.aligned.m16n8k16.row.col.f32.f16.f16.f32 "
        "{%0,%1,%2,%3}, {%4,%5,%6,%7}, {%8,%9}, {%0,%1,%2,%3};"
        : "+f"(d[0]), "+f"(d[1]), "+f"(d[2]), "+f"(d[3])
        : "r"(a[0]), "r"(a[1]), "r"(a[2]), "r"(a[3]), "r"(b[0]), "r"(b[1]));
}
__device__ __forceinline__ uint32_t pack_h2(float x, float y) {
    __half2 h = __floats2half2_rn(x, y);
    return *reinterpret_cast<uint32_t*>(&h);
}

// ---------------------------------------------------------------------------
// Prep: fused fp32 -> fp16 convert of x, W_qkv, W_out (one launch)
// blocks [0,8192): x, [8192,11264): W_qkv, [11264,12288): W_out
// ---------------------------------------------------------------------------
__global__ void convert_all_kernel(const float* __restrict__ x,
                                   const float* __restrict__ wqkv,
                                   const float* __restrict__ wout)
{
    int blk = blockIdx.x;
    const float* src;
    __half* dst;
    size_t off;
    if (blk < 8192)        { src = x;    dst = g_xh;    off = (size_t)blk * 1024; }
    else if (blk < 11264)  { src = wqkv; dst = g_wqkvh; off = (size_t)(blk - 8192) * 1024; }
    else                   { src = wout; dst = g_wouth; off = (size_t)(blk - 11264) * 1024; }
    size_t i = off + (size_t)threadIdx.x * 4;
    float4 v = *reinterpret_cast<const float4*>(src + i);
    *reinterpret_cast<__half2*>(&dst[i])     = __floats2half2_rn(v.x, v.y);
    *reinterpret_cast<__half2*>(&dst[i + 2]) = __floats2half2_rn(v.z, v.w);
}

// ---------------------------------------------------------------------------
// Raw mma.sync GEMM (unchanged from R6): C[M,N] = A[M,1024] @ B[1024,N] + bias
// ---------------------------------------------------------------------------
#define GBK 64
#define LDA 72
#define LDB 136
#define ASTG (128 * LDA)
#define BSTG (GBK * LDB)
#define GEMM_SMEM ((3 * (ASTG + BSTG)) * 2)

__device__ __forceinline__ void gemm_fill(
    const __half* __restrict__ A, const __half* __restrict__ B,
    __half* As, __half* Bs, int N, int m0, int n0, int k0, int tid)
{
    #pragma unroll
    for (int i = 0; i < 4; i++) {
        int idx = tid + i * 256;
        int r = idx >> 3, c = (idx & 7) * 8;
        cp_async16(&As[r * LDA + c], A + (size_t)(m0 + r) * DIM + k0 + c);
    }
    #pragma unroll
    for (int i = 0; i < 4; i++) {
        int idx = tid + i * 256;
        int r = idx >> 4, c = (idx & 15) * 8;
        cp_async16(&Bs[r * LDB + c], B + (size_t)(k0 + r) * N + n0 + c);
    }
}

__global__ __launch_bounds__(256, 2) void gemm_h16(
    const float* __restrict__ bias, float* __restrict__ C, int N, int mode)
{
    extern __shared__ __half hsm[];
    __half* Asm = hsm;
    __half* Bsm = hsm + 3 * ASTG;

    const int tid  = threadIdx.x;
    const int warp = tid >> 5;
    const int lane = tid & 31;
    const int wm   = warp & 3;
    const int wn   = warp >> 2;
    const int g    = lane >> 2;
    const int t4   = lane & 3;
    const int sub  = lane >> 3;
    const int rr   = lane & 7;
    const int m0   = blockIdx.y * 128;
    const int n0   = blockIdx.x * 128;

    const __half* A = (mode == 1) ? g_xh : g_attn;
    const __half* B = (mode == 1) ? g_wqkvh : g_wouth;

    float acc[2][8][4];
    #pragma unroll
    for (int mt = 0; mt < 2; mt++)
        #pragma unroll
        for (int nt = 0; nt < 8; nt++)
            #pragma unroll
            for (int e = 0; e < 4; e++) acc[mt][nt][e] = 0.0f;

    const int nk = DIM / GBK;
    gemm_fill(A, B, Asm, Bsm, N, m0, n0, 0, tid);
    CP_COMMIT();
    gemm_fill(A, B, Asm + ASTG, Bsm + BSTG, N, m0, n0, GBK, tid);
    CP_COMMIT();

    for (int t = 0; t < nk; t++) {
        if (t < nk - 2) { CP_WAIT(1); } else { CP_WAIT(0); }
        __syncthreads();
        if (t + 2 < nk) {
            int st = (t + 2) % 3;
            gemm_fill(A, B, Asm + st * ASTG, Bsm + st * BSTG, N, m0, n0, (t + 2) * GBK, tid);
            CP_COMMIT();
        }

        const __half* As = Asm + (t % 3) * ASTG;
        const __half* Bs = Bsm + (t % 3) * BSTG;

        #pragma unroll
        for (int ks = 0; ks < 4; ks++) {
            uint32_t Af[2][4];
            #pragma unroll
            for (int mt = 0; mt < 2; mt++) {
                uint32_t a = smem_addr(&As[(wm * 32 + mt * 16 + (sub & 1) * 8 + rr) * LDA
                                           + ks * 16 + (sub >> 1) * 8]);
                ldsm_x4(Af[mt], a);
            }
            uint32_t Bf[4][4];
            #pragma unroll
            for (int p = 0; p < 4; p++) {
                uint32_t a = smem_addr(&Bs[(ks * 16 + (sub & 1) * 8 + rr) * LDB
                                           + wn * 64 + p * 16 + (sub >> 1) * 8]);
                ldsm_x4_t(Bf[p], a);
            }
            #pragma unroll
            for (int mt = 0; mt < 2; mt++)
                #pragma unroll
                for (int p = 0; p < 4; p++) {
                    mma_16816(acc[mt][2 * p],     Af[mt], &Bf[p][0]);
                    mma_16816(acc[mt][2 * p + 1], Af[mt], &Bf[p][2]);
                }
        }
    }

    if (mode == 1) {
        #pragma unroll
        for (int nt = 0; nt < 8; nt++) {
            const int gn = n0 + wn * 64 + nt * 8 + 2 * t4;
            const int which = gn >> 10;
            const int d = gn & 1023;
            const int h = d >> 6;
            const int hd = d & 63;
            const float scale = (which == 0) ? 0.125f : 1.0f;
            const float b0 = bias[gn] * scale;
            const float b1 = bias[gn + 1] * scale;
            #pragma unroll
            for (int mt = 0; mt < 2; mt++) {
                int r0 = m0 + wm * 32 + mt * 16 + g;
                int bb = r0 >> 11;
                int ss = r0 & 2047;
                __half* d0 = &g_qkv[((((size_t)which * BATCH + bb) * HEADS + h) * SEQ + ss) * HDIM + hd];
                __half* d1 = &g_qkv[((((size_t)which * BATCH + bb) * HEADS + h) * SEQ + ss + 8) * HDIM + hd];
                *reinterpret_cast<uint32_t*>(d0) =
                    pack_h2(acc[mt][nt][0] * scale + b0, acc[mt][nt][1] * scale + b1);
                *reinterpret_cast<uint32_t*>(d1) =
                    pack_h2(acc[mt][nt][2] * scale + b0, acc[mt][nt][3] * scale + b1);
            }
        }
    } else {
        #pragma unroll
        for (int nt = 0; nt < 8; nt++) {
            const int gn = n0 + wn * 64 + nt * 8 + 2 * t4;
            const float b0 = bias[gn];
            const float b1 = bias[gn + 1];
            #pragma unroll
            for (int mt = 0; mt < 2; mt++) {
                int r0 = m0 + wm * 32 + mt * 16 + g;
                float2 v0 = { acc[mt][nt][0] + b0, acc[mt][nt][1] + b1 };
                float2 v1 = { acc[mt][nt][2] + b0, acc[mt][nt][3] + b1 };
                *reinterpret_cast<float2*>(&C[(size_t)r0 * N + gn]) = v0;
                *reinterpret_cast<float2*>(&C[(size_t)(r0 + 8) * N + gn]) = v1;
            }
        }
    }
}

// ---------------------------------------------------------------------------
// Register-resident FA2 flash attention, q-tile 128 (32 rows/warp, 2 m-tiles).
// K/V ldmatrix fragments amortized over both m-tiles; warp-level causal skip.
// ---------------------------------------------------------------------------
#define FST 72   // smem stride in halves
#define FLASH_SMEM ((128 * FST + 4 * 64 * FST) * 2)   // 55296 B -> 4 CTAs/SM

__global__ __launch_bounds__(128) void flash_attn(const int* __restrict__ flag_ptr)
{
    extern __shared__ __half fsm[];
    __half* Qs = fsm;                          // [128][FST]
    __half* Ks0 = Qs + 128 * FST;              // [64][FST] x2
    __half* Vs0 = Ks0 + 2 * 64 * FST;          // [64][FST] x2

    const int qt = blockIdx.x;                 // q-tile of 128 rows
    const int bh = blockIdx.y;
    const int b  = bh >> 4;
    const int h  = bh & 15;
    const int tid  = threadIdx.x;
    const int w    = tid >> 5;
    const int lane = tid & 31;
    const int g    = lane >> 2;
    const int t4   = lane & 3;
    const int sub  = lane >> 3;
    const int rr   = lane & 7;

    // ---- Load Q tile (128x64 fp16, pre-scaled) ----
    const __half* qg = g_qkv + (((size_t)b * HEADS + h) * SEQ + qt * 128) * HDIM;
    #pragma unroll
    for (int i = 0; i < 8; i++) {
        int idx = tid + i * 128;
        int r = idx >> 3, c = (idx & 7) * 8;
        *reinterpret_cast<uint4*>(&Qs[r * FST + c]) =
            *reinterpret_cast<const uint4*>(qg + r * 64 + c);
    }
    __syncthreads();

    // ---- Q A-fragments: 2 m-tiles x 4 k-chunks ----
    uint32_t QA[2][4][4];
    #pragma unroll
    for (int mt = 0; mt < 2; mt++)
        #pragma unroll
        for (int c = 0; c < 4; c++) {
            uint32_t a = smem_addr(&Qs[(w * 32 + mt * 16 + (sub & 1) * 8 + rr) * FST
                                       + c * 16 + (sub >> 1) * 8]);
            ldsm_x4(QA[mt][c], a);
        }

    // ---- State ----
    float O[2][8][4];
    #pragma unroll
    for (int mt = 0; mt < 2; mt++)
        #pragma unroll
        for (int j = 0; j < 8; j++)
            #pragma unroll
            for (int e = 0; e < 4; e++) O[mt][j][e] = 0.0f;
    float mst[2][2] = { { -1e30f, -1e30f }, { -1e30f, -1e30f } };
    float lst[2][2] = { { 0.0f, 0.0f }, { 0.0f, 0.0f } };

    const int causal = *flag_ptr;
    const int ktmax = causal ? (2 * qt + 1) : (SEQ / 64 - 1);
    const int qrow[2] = { qt * 128 + w * 32 + g, qt * 128 + w * 32 + 16 + g };
    const int wrow_min = qt * 128 + w * 32;
    const int wrow_max = wrow_min + 31;

    const __half* kgbase = g_qkv + ((((size_t)1 * BATCH + b) * HEADS + h) * SEQ) * HDIM;
    const __half* vgbase = g_qkv + ((((size_t)2 * BATCH + b) * HEADS + h) * SEQ) * HDIM;

    // ---- Prefetch kt = 0 ----
    #pragma unroll
    for (int i = 0; i < 4; i++) {
        int idx = tid + i * 128;
        int r = idx >> 3, c = (idx & 7) * 8;
        cp_async16(&Ks0[r * FST + c], kgbase + r * 64 + c);
        cp_async16(&Vs0[r * FST + c], vgbase + r * 64 + c);
    }
    CP_COMMIT();

    for (int kt = 0; kt <= ktmax; kt++) {
        if (kt + 1 <= ktmax) {
            const __half* kg = kgbase + (size_t)(kt + 1) * 64 * HDIM;
            const __half* vg = vgbase + (size_t)(kt + 1) * 64 * HDIM;
            int nb = (kt + 1) & 1;
            #pragma unroll
            for (int i = 0; i < 4; i++) {
                int idx = tid + i * 128;
                int r = idx >> 3, c = (idx & 7) * 8;
                cp_async16(&Ks0[nb * 64 * FST + r * FST + c], kg + r * 64 + c);
                cp_async16(&Vs0[nb * 64 * FST + r * FST + c], vg + r * 64 + c);
            }
            CP_COMMIT();
            CP_WAIT(1);
        } else {
            CP_WAIT(0);
        }
        __syncthreads();

        // Warp-level causal skip: this warp's rows all above this kt tile
        if (!causal || kt * 64 <= wrow_max) {
            const __half* Kb = Ks0 + (kt & 1) * 64 * FST;
            const __half* Vb = Vs0 + (kt & 1) * 64 * FST;

            // ---- S = Q @ K^T, both m-tiles share K fragments ----
            float S[2][8][4];
            #pragma unroll
            for (int mt = 0; mt < 2; mt++)
                #pragma unroll
                for (int j = 0; j < 8; j++)
                    #pragma unroll
                    for (int e = 0; e < 4; e++) S[mt][j][e] = 0.0f;

            #pragma unroll
            for (int p = 0; p < 4; p++) {
                #pragma unroll
                for (int c = 0; c < 4; c++) {
                    uint32_t Bf[4];
                    uint32_t a = smem_addr(&Kb[((2 * p + (sub >> 1)) * 8 + rr) * FST
                                               + c * 16 + (sub & 1) * 8]);
                    ldsm_x4(Bf, a);
                    #pragma unroll
                    for (int mt = 0; mt < 2; mt++) {
                        mma_16816(S[mt][2 * p],     QA[mt][c], &Bf[0]);
                        mma_16816(S[mt][2 * p + 1], QA[mt][c], &Bf[2]);
                    }
                }
            }

            // ---- Causal mask (tiles overlapping the diagonal) ----
            if (causal && kt * 64 + 63 > wrow_min) {
                #pragma unroll
                for (int mt = 0; mt < 2; mt++)
                    #pragma unroll
                    for (int j = 0; j < 8; j++) {
                        int col = kt * 64 + j * 8 + 2 * t4;
                        if (col > qrow[mt])         S[mt][j][0] = -1e30f;
                        if (col + 1 > qrow[mt])     S[mt][j][1] = -1e30f;
                        if (col > qrow[mt] + 8)     S[mt][j][2] = -1e30f;
                        if (col + 1 > qrow[mt] + 8) S[mt][j][3] = -1e30f;
                    }
            }

            // ---- Online softmax per m-tile ----
            #pragma unroll
            for (int mt = 0; mt < 2; mt++) {
                float mx0 = -1e30f, mx1 = -1e30f;
                #pragma unroll
                for (int j = 0; j < 8; j++) {
                    mx0 = fmaxf(mx0, fmaxf(S[mt][j][0], S[mt][j][1]));
                    mx1 = fmaxf(mx1, fmaxf(S[mt][j][2], S[mt][j][3]));
                }
                mx0 = fmaxf(mx0, __shfl_xor_sync(0xffffffffu, mx0, 1));
                mx0 = fmaxf(mx0, __shfl_xor_sync(0xffffffffu, mx0, 2));
                mx1 = fmaxf(mx1, __shfl_xor_sync(0xffffffffu, mx1, 1));
                mx1 = fmaxf(mx1, __shfl_xor_sync(0xffffffffu, mx1, 2));

                float mn0 = fmaxf(mst[mt][0], mx0);
                float mn1 = fmaxf(mst[mt][1], mx1);
                float a0 = __expf(mst[mt][0] - mn0);
                float a1 = __expf(mst[mt][1] - mn1);

                float s0 = 0.0f, s1 = 0.0f;
                #pragma unroll
                for (int j = 0; j < 8; j++) {
                    S[mt][j][0] = __expf(S[mt][j][0] - mn0);
                    S[mt][j][1] = __expf(S[mt][j][1] - mn0);
                    S[mt][j][2] = __expf(S[mt][j][2] - mn1);
                    S[mt][j][3] = __expf(S[mt][j][3] - mn1);
                    s0 += S[mt][j][0] + S[mt][j][1];
                    s1 += S[mt][j][2] + S[mt][j][3];
                }
                s0 += __shfl_xor_sync(0xffffffffu, s0, 1);
                s0 += __shfl_xor_sync(0xffffffffu, s0, 2);
                s1 += __shfl_xor_sync(0xffffffffu, s1, 1);
                s1 += __shfl_xor_sync(0xffffffffu, s1, 2);

                lst[mt][0] = lst[mt][0] * a0 + s0;
                lst[mt][1] = lst[mt][1] * a1 + s1;
                mst[mt][0] = mn0;
                mst[mt][1] = mn1;

                #pragma unroll
                for (int j = 0; j < 8; j++) {
                    O[mt][j][0] *= a0; O[mt][j][1] *= a0;
                    O[mt][j][2] *= a1; O[mt][j][3] *= a1;
                }
            }

            // ---- O += P @ V, both m-tiles share V fragments ----
            #pragma unroll
            for (int c = 0; c < 4; c++) {
                uint32_t PA[2][4];
                #pragma unroll
                for (int mt = 0; mt < 2; mt++) {
                    PA[mt][0] = pack_h2(S[mt][2 * c][0],     S[mt][2 * c][1]);
                    PA[mt][1] = pack_h2(S[mt][2 * c][2],     S[mt][2 * c][3]);
                    PA[mt][2] = pack_h2(S[mt][2 * c + 1][0], S[mt][2 * c + 1][1]);
                    PA[mt][3] = pack_h2(S[mt][2 * c + 1][2], S[mt][2 * c + 1][3]);
                }
                #pragma unroll
                for (int jj = 0; jj < 8; jj += 2) {
                    uint32_t Bf[4];
                    uint32_t a = smem_addr(&Vb[(c * 16 + (sub & 1) * 8 + rr) * FST
                                               + (jj + (sub >> 1)) * 8]);
                    ldsm_x4_t(Bf, a);
                    #pragma unroll
                    for (int mt = 0; mt < 2; mt++) {
                        mma_16816(O[mt][jj],     PA[mt], &Bf[0]);
                        mma_16816(O[mt][jj + 1], PA[mt], &Bf[2]);
                    }
                }
            }
        }
        __syncthreads();
    }

    // ---- Epilogue: O / l -> g_attn fp16 ----
    #pragma unroll
    for (int mt = 0; mt < 2; mt++) {
        float inv0 = 1.0f / lst[mt][0];
        float inv1 = 1.0f / lst[mt][1];
        __half* d0 = g_attn + ((size_t)b * SEQ + qrow[mt]) * DIM + h * HDIM;
        __half* d1 = g_attn + ((size_t)b * SEQ + qrow[mt] + 8) * DIM + h * HDIM;
        #pragma unroll
        for (int j = 0; j < 8; j++) {
            int hd = j * 8 + 2 * t4;
            *reinterpret_cast<uint32_t*>(d0 + hd) = pack_h2(O[mt][j][0] * inv0, O[mt][j][1] * inv0);
            *reinterpret_cast<uint32_t*>(d1 + hd) = pack_h2(O[mt][j][2] * inv1, O[mt][j][3] * inv1);
        }
    }
}

// ---------------------------------------------------------------------------
extern "C" void kernel_launch(void* const* d_in, const int* in_sizes, int n_in,
                              void* d_out, int out_size)
{
    const float* x     = (const float*)d_in[0];
    const float* Wqkv  = (const float*)d_in[1];
    const float* bqkv  = (const float*)d_in[2];
    const float* Wout  = (const float*)d_in[3];
    const float* bout  = (const float*)d_in[4];
    const int*   flag  = (const int*)d_in[5];
    float*       out   = (float*)d_out;

    cudaFuncSetAttribute(gemm_h16, cudaFuncAttributeMaxDynamicSharedMemorySize, GEMM_SMEM);
    cudaFuncSetAttribute(flash_attn, cudaFuncAttributeMaxDynamicSharedMemorySize, FLASH_SMEM);

    // Prep: single fused fp32->fp16 conversion launch
    convert_all_kernel<<<12288, 256>>>(x, Wqkv, Wout);

    // 1) QKV projection -> g_qkv fp16 (Q scaled)
    dim3 g1(3 * DIM / 128, MROWS / 128);   // (24, 64)
    gemm_h16<<<g1, 256, GEMM_SMEM>>>(bqkv, nullptr, 3 * DIM, 1);

    // 2) Flash attention -> g_attn fp16
    dim3 g2(SEQ / 128, BATCH * HEADS);     // (16, 64)
    flash_attn<<<g2, 128, FLASH_SMEM>>>(flag);

    // 3) Output projection -> d_out fp32
    dim3 g3(DIM / 128, MROWS / 128);       // (8, 64)
    gemm_h16<<<g3, 256, GEMM_SMEM>>>(bout, out, DIM, 2);
}

// round 8
// speedup vs baseline: 6.1227x; 1.0028x over previous
#include <cuda_runtime.h>
#include <cuda_fp16.h>
#include <cstdint>

// Problem constants
#define BATCH 4
#define SEQ   2048
#define DIM   1024
#define HEADS 16
#define HDIM  64
#define MROWS (BATCH*SEQ)          // 8192

// ---------------------------------------------------------------------------
// Device-global scratch (no runtime allocation allowed)
// ---------------------------------------------------------------------------
__device__ __half g_xh[(size_t)MROWS * DIM];
__device__ __half g_wqkvh[(size_t)DIM * 3 * DIM];
__device__ __half g_wouth[(size_t)DIM * DIM];
__device__ __half g_qkv[(size_t)3 * BATCH * HEADS * SEQ * HDIM];   // [which][b][h][s][hd], Q pre-scaled
__device__ __half g_attn[(size_t)MROWS * DIM];

// ---------------------------------------------------------------------------
// helpers
// ---------------------------------------------------------------------------
__device__ __forceinline__ void cp_async16(void* smem_dst, const void* gmem_src) {
    uint32_t s = (uint32_t)__cvta_generic_to_shared(smem_dst);
    asm volatile("cp.async.cg.shared.global [%0], [%1], 16;\n" :: "r"(s), "l"(gmem_src));
}
#define CP_COMMIT() asm volatile("cp.async.commit_group;\n" ::: "memory")
#define CP_WAIT(n)  asm volatile("cp.async.wait_group %0;\n" :: "n"(n) : "memory")

__device__ __forceinline__ uint32_t smem_addr(const void* p) {
    return (uint32_t)__cvta_generic_to_shared(p);
}
__device__ __forceinline__ void ldsm_x4(uint32_t* r, uint32_t a) {
    asm volatile("ldmatrix.sync.aligned.m8n8.x4.shared.b16 {%0,%1,%2,%3}, [%4];"
                 : "=r"(r[0]), "=r"(r[1]), "=r"(r[2]), "=r"(r[3]) : "r"(a));
}
__device__ __forceinline__ void ldsm_x4_t(uint32_t* r, uint32_t a) {
    asm volatile("ldmatrix.sync.aligned.m8n8.x4.trans.shared.b16 {%0,%1,%2,%3}, [%4];"
                 : "=r"(r[0]), "=r"(r[1]), "=r"(r[2]), "=r"(r[3]) : "r"(a));
}
__device__ __forceinline__ void mma_16816(float* d, const uint32_t* a, const uint32_t* b) {
    asm volatile(
        "mma.sync.aligned.m16n8k16.row.col.f32.f16.f16.f32 "
        "{%0,%1,%2,%3}, {%4,%5,%6,%7}, {%8,%9}, {%0,%1,%2,%3};"
        : "+f"(d[0]), "+f"(d[1]), "+f"(d[2]), "+f"(d[3])
        : "r"(a[0]), "r"(a[1]), "r"(a[2]), "r"(a[3]), "r"(b[0]), "r"(b[1]));
}
__device__ __forceinline__ uint32_t pack_h2(float x, float y) {
    __half2 h = __floats2half2_rn(x, y);
    return *reinterpret_cast<uint32_t*>(&h);
}

// ---------------------------------------------------------------------------
// Prep: fused fp32 -> fp16 convert of x, W_qkv, W_out (one launch)
// ---------------------------------------------------------------------------
__global__ void convert_all_kernel(const float* __restrict__ x,
                                   const float* __restrict__ wqkv,
                                   const float* __restrict__ wout)
{
    int blk = blockIdx.x;
    const float* src;
    __half* dst;
    size_t off;
    if (blk < 8192)        { src = x;    dst = g_xh;    off = (size_t)blk * 1024; }
    else if (blk < 11264)  { src = wqkv; dst = g_wqkvh; off = (size_t)(blk - 8192) * 1024; }
    else                   { src = wout; dst = g_wouth; off = (size_t)(blk - 11264) * 1024; }
    size_t i = off + (size_t)threadIdx.x * 4;
    float4 v = *reinterpret_cast<const float4*>(src + i);
    *reinterpret_cast<__half2*>(&dst[i])     = __floats2half2_rn(v.x, v.y);
    *reinterpret_cast<__half2*>(&dst[i + 2]) = __floats2half2_rn(v.z, v.w);
}

// ---------------------------------------------------------------------------
// Raw mma.sync GEMM: C[M,N] = A[M,1024] @ B[1024,N] + bias
// CTA tile 128x128, BK=64, 3-stage cp.async, 128 threads = 4 warps of 64x64.
// Per ks-step: 8 LDSM.x4 feed 32 HMMA (4:1) for latency hiding.
// ---------------------------------------------------------------------------
#define GBK 64
#define LDA 72
#define LDB 136
#define ASTG (128 * LDA)
#define BSTG (GBK * LDB)
#define GEMM_SMEM ((3 * (ASTG + BSTG)) * 2)   // 107520 B -> 2 CTAs/SM

__device__ __forceinline__ void gemm_fill(
    const __half* __restrict__ A, const __half* __restrict__ B,
    __half* As, __half* Bs, int N, int m0, int n0, int k0, int tid)
{
    #pragma unroll
    for (int i = 0; i < 8; i++) {
        int idx = tid + i * 128;
        int r = idx >> 3, c = (idx & 7) * 8;
        cp_async16(&As[r * LDA + c], A + (size_t)(m0 + r) * DIM + k0 + c);
    }
    #pragma unroll
    for (int i = 0; i < 8; i++) {
        int idx = tid + i * 128;
        int r = idx >> 4, c = (idx & 15) * 8;
        cp_async16(&Bs[r * LDB + c], B + (size_t)(k0 + r) * N + n0 + c);
    }
}

__global__ __launch_bounds__(128) void gemm_h16(
    const float* __restrict__ bias, float* __restrict__ C, int N, int mode)
{
    extern __shared__ __half hsm[];
    __half* Asm = hsm;
    __half* Bsm = hsm + 3 * ASTG;

    const int tid  = threadIdx.x;
    const int warp = tid >> 5;
    const int lane = tid & 31;
    const int wm   = warp & 1;        // 64-row band
    const int wn   = warp >> 1;       // 64-col band
    const int g    = lane >> 2;
    const int t4   = lane & 3;
    const int sub  = lane >> 3;
    const int rr   = lane & 7;
    const int m0   = blockIdx.y * 128;
    const int n0   = blockIdx.x * 128;

    const __half* A = (mode == 1) ? g_xh : g_attn;
    const __half* B = (mode == 1) ? g_wqkvh : g_wouth;

    float acc[4][8][4];
    #pragma unroll
    for (int mt = 0; mt < 4; mt++)
        #pragma unroll
        for (int nt = 0; nt < 8; nt++)
            #pragma unroll
            for (int e = 0; e < 4; e++) acc[mt][nt][e] = 0.0f;

    const int nk = DIM / GBK;
    gemm_fill(A, B, Asm, Bsm, N, m0, n0, 0, tid);
    CP_COMMIT();
    gemm_fill(A, B, Asm + ASTG, Bsm + BSTG, N, m0, n0, GBK, tid);
    CP_COMMIT();

    for (int t = 0; t < nk; t++) {
        if (t < nk - 2) { CP_WAIT(1); } else { CP_WAIT(0); }
        __syncthreads();
        if (t + 2 < nk) {
            int st = (t + 2) % 3;
            gemm_fill(A, B, Asm + st * ASTG, Bsm + st * BSTG, N, m0, n0, (t + 2) * GBK, tid);
            CP_COMMIT();
        }

        const __half* As = Asm + (t % 3) * ASTG;
        const __half* Bs = Bsm + (t % 3) * BSTG;

        #pragma unroll
        for (int ks = 0; ks < 4; ks++) {
            uint32_t Af[4][4];
            #pragma unroll
            for (int mt = 0; mt < 4; mt++) {
                uint32_t a = smem_addr(&As[(wm * 64 + mt * 16 + (sub & 1) * 8 + rr) * LDA
                                           + ks * 16 + (sub >> 1) * 8]);
                ldsm_x4(Af[mt], a);
            }
            uint32_t Bf[4][4];
            #pragma unroll
            for (int p = 0; p < 4; p++) {
                uint32_t a = smem_addr(&Bs[(ks * 16 + (sub & 1) * 8 + rr) * LDB
                                           + wn * 64 + p * 16 + (sub >> 1) * 8]);
                ldsm_x4_t(Bf[p], a);
            }
            #pragma unroll
            for (int mt = 0; mt < 4; mt++)
                #pragma unroll
                for (int p = 0; p < 4; p++) {
                    mma_16816(acc[mt][2 * p],     Af[mt], &Bf[p][0]);
                    mma_16816(acc[mt][2 * p + 1], Af[mt], &Bf[p][2]);
                }
        }
    }

    if (mode == 1) {
        #pragma unroll
        for (int nt = 0; nt < 8; nt++) {
            const int gn = n0 + wn * 64 + nt * 8 + 2 * t4;
            const int which = gn >> 10;
            const int d = gn & 1023;
            const int h = d >> 6;
            const int hd = d & 63;
            const float scale = (which == 0) ? 0.125f : 1.0f;
            const float b0 = bias[gn] * scale;
            const float b1 = bias[gn + 1] * scale;
            #pragma unroll
            for (int mt = 0; mt < 4; mt++) {
                int r0 = m0 + wm * 64 + mt * 16 + g;
                int bb = r0 >> 11;
                int ss = r0 & 2047;
                __half* d0 = &g_qkv[((((size_t)which * BATCH + bb) * HEADS + h) * SEQ + ss) * HDIM + hd];
                __half* d1 = &g_qkv[((((size_t)which * BATCH + bb) * HEADS + h) * SEQ + ss + 8) * HDIM + hd];
                *reinterpret_cast<uint32_t*>(d0) =
                    pack_h2(acc[mt][nt][0] * scale + b0, acc[mt][nt][1] * scale + b1);
                *reinterpret_cast<uint32_t*>(d1) =
                    pack_h2(acc[mt][nt][2] * scale + b0, acc[mt][nt][3] * scale + b1);
            }
        }
    } else {
        #pragma unroll
        for (int nt = 0; nt < 8; nt++) {
            const int gn = n0 + wn * 64 + nt * 8 + 2 * t4;
            const float b0 = bias[gn];
            const float b1 = bias[gn + 1];
            #pragma unroll
            for (int mt = 0; mt < 4; mt++) {
                int r0 = m0 + wm * 64 + mt * 16 + g;
                float2 v0 = { acc[mt][nt][0] + b0, acc[mt][nt][1] + b1 };
                float2 v1 = { acc[mt][nt][2] + b0, acc[mt][nt][3] + b1 };
                *reinterpret_cast<float2*>(&C[(size_t)r0 * N + gn]) = v0;
                *reinterpret_cast<float2*>(&C[(size_t)(r0 + 8) * N + gn]) = v1;
            }
        }
    }
}

// ---------------------------------------------------------------------------
// Register-resident FA2 flash attention (unchanged from R7).
// ---------------------------------------------------------------------------
#define FST 72   // smem stride in halves
#define FLASH_SMEM ((128 * FST + 4 * 64 * FST) * 2)   // 55296 B

__global__ __launch_bounds__(128) void flash_attn(const int* __restrict__ flag_ptr)
{
    extern __shared__ __half fsm[];
    __half* Qs = fsm;
    __half* Ks0 = Qs + 128 * FST;
    __half* Vs0 = Ks0 + 2 * 64 * FST;

    const int qt = blockIdx.x;
    const int bh = blockIdx.y;
    const int b  = bh >> 4;
    const int h  = bh & 15;
    const int tid  = threadIdx.x;
    const int w    = tid >> 5;
    const int lane = tid & 31;
    const int g    = lane >> 2;
    const int t4   = lane & 3;
    const int sub  = lane >> 3;
    const int rr   = lane & 7;

    const __half* qg = g_qkv + (((size_t)b * HEADS + h) * SEQ + qt * 128) * HDIM;
    #pragma unroll
    for (int i = 0; i < 8; i++) {
        int idx = tid + i * 128;
        int r = idx >> 3, c = (idx & 7) * 8;
        *reinterpret_cast<uint4*>(&Qs[r * FST + c]) =
            *reinterpret_cast<const uint4*>(qg + r * 64 + c);
    }
    __syncthreads();

    uint32_t QA[2][4][4];
    #pragma unroll
    for (int mt = 0; mt < 2; mt++)
        #pragma unroll
        for (int c = 0; c < 4; c++) {
            uint32_t a = smem_addr(&Qs[(w * 32 + mt * 16 + (sub & 1) * 8 + rr) * FST
                                       + c * 16 + (sub >> 1) * 8]);
            ldsm_x4(QA[mt][c], a);
        }

    float O[2][8][4];
    #pragma unroll
    for (int mt = 0; mt < 2; mt++)
        #pragma unroll
        for (int j = 0; j < 8; j++)
            #pragma unroll
            for (int e = 0; e < 4; e++) O[mt][j][e] = 0.0f;
    float mst[2][2] = { { -1e30f, -1e30f }, { -1e30f, -1e30f } };
    float lst[2][2] = { { 0.0f, 0.0f }, { 0.0f, 0.0f } };

    const int causal = *flag_ptr;
    const int ktmax = causal ? (2 * qt + 1) : (SEQ / 64 - 1);
    const int qrow[2] = { qt * 128 + w * 32 + g, qt * 128 + w * 32 + 16 + g };
    const int wrow_min = qt * 128 + w * 32;
    const int wrow_max = wrow_min + 31;

    const __half* kgbase = g_qkv + ((((size_t)1 * BATCH + b) * HEADS + h) * SEQ) * HDIM;
    const __half* vgbase = g_qkv + ((((size_t)2 * BATCH + b) * HEADS + h) * SEQ) * HDIM;

    #pragma unroll
    for (int i = 0; i < 4; i++) {
        int idx = tid + i * 128;
        int r = idx >> 3, c = (idx & 7) * 8;
        cp_async16(&Ks0[r * FST + c], kgbase + r * 64 + c);
        cp_async16(&Vs0[r * FST + c], vgbase + r * 64 + c);
    }
    CP_COMMIT();

    for (int kt = 0; kt <= ktmax; kt++) {
        if (kt + 1 <= ktmax) {
            const __half* kg = kgbase + (size_t)(kt + 1) * 64 * HDIM;
            const __half* vg = vgbase + (size_t)(kt + 1) * 64 * HDIM;
            int nb = (kt + 1) & 1;
            #pragma unroll
            for (int i = 0; i < 4; i++) {
                int idx = tid + i * 128;
                int r = idx >> 3, c = (idx & 7) * 8;
                cp_async16(&Ks0[nb * 64 * FST + r * FST + c], kg + r * 64 + c);
                cp_async16(&Vs0[nb * 64 * FST + r * FST + c], vg + r * 64 + c);
            }
            CP_COMMIT();
            CP_WAIT(1);
        } else {
            CP_WAIT(0);
        }
        __syncthreads();

        if (!causal || kt * 64 <= wrow_max) {
            const __half* Kb = Ks0 + (kt & 1) * 64 * FST;
            const __half* Vb = Vs0 + (kt & 1) * 64 * FST;

            float S[2][8][4];
            #pragma unroll
            for (int mt = 0; mt < 2; mt++)
                #pragma unroll
                for (int j = 0; j < 8; j++)
                    #pragma unroll
                    for (int e = 0; e < 4; e++) S[mt][j][e] = 0.0f;

            #pragma unroll
            for (int p = 0; p < 4; p++) {
                #pragma unroll
                for (int c = 0; c < 4; c++) {
                    uint32_t Bf[4];
                    uint32_t a = smem_addr(&Kb[((2 * p + (sub >> 1)) * 8 + rr) * FST
                                               + c * 16 + (sub & 1) * 8]);
                    ldsm_x4(Bf, a);
                    #pragma unroll
                    for (int mt = 0; mt < 2; mt++) {
                        mma_16816(S[mt][2 * p],     QA[mt][c], &Bf[0]);
                        mma_16816(S[mt][2 * p + 1], QA[mt][c], &Bf[2]);
                    }
                }
            }

            if (causal && kt * 64 + 63 > wrow_min) {
                #pragma unroll
                for (int mt = 0; mt < 2; mt++)
                    #pragma unroll
                    for (int j = 0; j < 8; j++) {
                        int col = kt * 64 + j * 8 + 2 * t4;
                        if (col > qrow[mt])         S[mt][j][0] = -1e30f;
                        if (col + 1 > qrow[mt])     S[mt][j][1] = -1e30f;
                        if (col > qrow[mt] + 8)     S[mt][j][2] = -1e30f;
                        if (col + 1 > qrow[mt] + 8) S[mt][j][3] = -1e30f;
                    }
            }

            #pragma unroll
            for (int mt = 0; mt < 2; mt++) {
                float mx0 = -1e30f, mx1 = -1e30f;
                #pragma unroll
                for (int j = 0; j < 8; j++) {
                    mx0 = fmaxf(mx0, fmaxf(S[mt][j][0], S[mt][j][1]));
                    mx1 = fmaxf(mx1, fmaxf(S[mt][j][2], S[mt][j][3]));
                }
                mx0 = fmaxf(mx0, __shfl_xor_sync(0xffffffffu, mx0, 1));
                mx0 = fmaxf(mx0, __shfl_xor_sync(0xffffffffu, mx0, 2));
                mx1 = fmaxf(mx1, __shfl_xor_sync(0xffffffffu, mx1, 1));
                mx1 = fmaxf(mx1, __shfl_xor_sync(0xffffffffu, mx1, 2));

                float mn0 = fmaxf(mst[mt][0], mx0);
                float mn1 = fmaxf(mst[mt][1], mx1);
                float a0 = __expf(mst[mt][0] - mn0);
                float a1 = __expf(mst[mt][1] - mn1);

                float s0 = 0.0f, s1 = 0.0f;
                #pragma unroll
                for (int j = 0; j < 8; j++) {
                    S[mt][j][0] = __expf(S[mt][j][0] - mn0);
                    S[mt][j][1] = __expf(S[mt][j][1] - mn0);
                    S[mt][j][2] = __expf(S[mt][j][2] - mn1);
                    S[mt][j][3] = __expf(S[mt][j][3] - mn1);
                    s0 += S[mt][j][0] + S[mt][j][1];
                    s1 += S[mt][j][2] + S[mt][j][3];
                }
                s0 += __shfl_xor_sync(0xffffffffu, s0, 1);
                s0 += __shfl_xor_sync(0xffffffffu, s0, 2);
                s1 += __shfl_xor_sync(0xffffffffu, s1, 1);
                s1 += __shfl_xor_sync(0xffffffffu, s1, 2);

                lst[mt][0] = lst[mt][0] * a0 + s0;
                lst[mt][1] = lst[mt][1] * a1 + s1;
                mst[mt][0] = mn0;
                mst[mt][1] = mn1;

                #pragma unroll
                for (int j = 0; j < 8; j++) {
                    O[mt][j][0] *= a0; O[mt][j][1] *= a0;
                    O[mt][j][2] *= a1; O[mt][j][3] *= a1;
                }
            }

            #pragma unroll
            for (int c = 0; c < 4; c++) {
                uint32_t PA[2][4];
                #pragma unroll
                for (int mt = 0; mt < 2; mt++) {
                    PA[mt][0] = pack_h2(S[mt][2 * c][0],     S[mt][2 * c][1]);
                    PA[mt][1] = pack_h2(S[mt][2 * c][2],     S[mt][2 * c][3]);
                    PA[mt][2] = pack_h2(S[mt][2 * c + 1][0], S[mt][2 * c + 1][1]);
                    PA[mt][3] = pack_h2(S[mt][2 * c + 1][2], S[mt][2 * c + 1][3]);
                }
                #pragma unroll
                for (int jj = 0; jj < 8; jj += 2) {
                    uint32_t Bf[4];
                    uint32_t a = smem_addr(&Vb[(c * 16 + (sub & 1) * 8 + rr) * FST
                                               + (jj + (sub >> 1)) * 8]);
                    ldsm_x4_t(Bf, a);
                    #pragma unroll
                    for (int mt = 0; mt < 2; mt++) {
                        mma_16816(O[mt][jj],     PA[mt], &Bf[0]);
                        mma_16816(O[mt][jj + 1], PA[mt], &Bf[2]);
                    }
                }
            }
        }
        __syncthreads();
    }

    #pragma unroll
    for (int mt = 0; mt < 2; mt++) {
        float inv0 = 1.0f / lst[mt][0];
        float inv1 = 1.0f / lst[mt][1];
        __half* d0 = g_attn + ((size_t)b * SEQ + qrow[mt]) * DIM + h * HDIM;
        __half* d1 = g_attn + ((size_t)b * SEQ + qrow[mt] + 8) * DIM + h * HDIM;
        #pragma unroll
        for (int j = 0; j < 8; j++) {
            int hd = j * 8 + 2 * t4;
            *reinterpret_cast<uint32_t*>(d0 + hd) = pack_h2(O[mt][j][0] * inv0, O[mt][j][1] * inv0);
            *reinterpret_cast<uint32_t*>(d1 + hd) = pack_h2(O[mt][j][2] * inv1, O[mt][j][3] * inv1);
        }
    }
}

// ---------------------------------------------------------------------------
extern "C" void kernel_launch(void* const* d_in, const int* in_sizes, int n_in,
                              void* d_out, int out_size)
{
    const float* x     = (const float*)d_in[0];
    const float* Wqkv  = (const float*)d_in[1];
    const float* bqkv  = (const float*)d_in[2];
    const float* Wout  = (const float*)d_in[3];
    const float* bout  = (const float*)d_in[4];
    const int*   flag  = (const int*)d_in[5];
    float*       out   = (float*)d_out;

    cudaFuncSetAttribute(gemm_h16, cudaFuncAttributeMaxDynamicSharedMemorySize, GEMM_SMEM);
    cudaFuncSetAttribute(flash_attn, cudaFuncAttributeMaxDynamicSharedMemorySize, FLASH_SMEM);

    convert_all_kernel<<<12288, 256>>>(x, Wqkv, Wout);

    dim3 g1(3 * DIM / 128, MROWS / 128);   // (24, 64)
    gemm_h16<<<g1, 128, GEMM_SMEM>>>(bqkv, nullptr, 3 * DIM, 1);

    dim3 g2(SEQ / 128, BATCH * HEADS);     // (16, 64)
    flash_attn<<<g2, 128, FLASH_SMEM>>>(flag);

    dim3 g3(DIM / 128, MROWS / 128);       // (8, 64)
    gemm_h16<<<g3, 128, GEMM_SMEM>>>(bout, out, DIM, 2);
}

// round 9
// speedup vs baseline: 6.3705x; 1.0405x over previous
#include <cuda_runtime.h>
#include <cuda_fp16.h>
#include <cstdint>

// Problem constants
#define BATCH 4
#define SEQ   2048
#define DIM   1024
#define HEADS 16
#define HDIM  64
#define MROWS (BATCH*SEQ)          // 8192

// ---------------------------------------------------------------------------
// Device-global scratch (no runtime allocation allowed)
// ---------------------------------------------------------------------------
__device__ __half g_xh[(size_t)MROWS * DIM];
__device__ __half g_wqkvh[(size_t)DIM * 3 * DIM];
__device__ __half g_wouth[(size_t)DIM * DIM];
__device__ __half g_qkv[(size_t)3 * BATCH * HEADS * SEQ * HDIM];   // [which][b][h][s][hd], Q pre-scaled
__device__ __half g_attn[(size_t)MROWS * DIM];

// ---------------------------------------------------------------------------
// helpers
// ---------------------------------------------------------------------------
__device__ __forceinline__ void cp_async16(void* smem_dst, const void* gmem_src) {
    uint32_t s = (uint32_t)__cvta_generic_to_shared(smem_dst);
    asm volatile("cp.async.cg.shared.global [%0], [%1], 16;\n" :: "r"(s), "l"(gmem_src));
}
#define CP_COMMIT() asm volatile("cp.async.commit_group;\n" ::: "memory")
#define CP_WAIT(n)  asm volatile("cp.async.wait_group %0;\n" :: "n"(n) : "memory")

__device__ __forceinline__ uint32_t smem_addr(const void* p) {
    return (uint32_t)__cvta_generic_to_shared(p);
}
__device__ __forceinline__ void ldsm_x4(uint32_t* r, uint32_t a) {
    asm volatile("ldmatrix.sync.aligned.m8n8.x4.shared.b16 {%0,%1,%2,%3}, [%4];"
                 : "=r"(r[0]), "=r"(r[1]), "=r"(r[2]), "=r"(r[3]) : "r"(a));
}
__device__ __forceinline__ void ldsm_x4_t(uint32_t* r, uint32_t a) {
    asm volatile("ldmatrix.sync.aligned.m8n8.x4.trans.shared.b16 {%0,%1,%2,%3}, [%4];"
                 : "=r"(r[0]), "=r"(r[1]), "=r"(r[2]), "=r"(r[3]) : "r"(a));
}
__device__ __forceinline__ void mma_16816(float* d, const uint32_t* a, const uint32_t* b) {
    asm volatile(
        "mma.sync.aligned.m16n8k16.row.col.f32.f16.f16.f32 "
        "{%0,%1,%2,%3}, {%4,%5,%6,%7}, {%8,%9}, {%0,%1,%2,%3};"
        : "+f"(d[0]), "+f"(d[1]), "+f"(d[2]), "+f"(d[3])
        : "r"(a[0]), "r"(a[1]), "r"(a[2]), "r"(a[3]), "r"(b[0]), "r"(b[1]));
}
__device__ __forceinline__ uint32_t pack_h2(float x, float y) {
    __half2 h = __floats2half2_rn(x, y);
    return *reinterpret_cast<uint32_t*>(&h);
}

// ---------------------------------------------------------------------------
// Prep: fused fp32 -> fp16 convert of x, W_qkv, W_out (one launch)
// ---------------------------------------------------------------------------
__global__ void convert_all_kernel(const float* __restrict__ x,
                                   const float* __restrict__ wqkv,
                                   const float* __restrict__ wout)
{
    int blk = blockIdx.x;
    const float* src;
    __half* dst;
    size_t off;
    if (blk < 8192)        { src = x;    dst = g_xh;    off = (size_t)blk * 1024; }
    else if (blk < 11264)  { src = wqkv; dst = g_wqkvh; off = (size_t)(blk - 8192) * 1024; }
    else                   { src = wout; dst = g_wouth; off = (size_t)(blk - 11264) * 1024; }
    size_t i = off + (size_t)threadIdx.x * 4;
    float4 v = *reinterpret_cast<const float4*>(src + i);
    *reinterpret_cast<__half2*>(&dst[i])     = __floats2half2_rn(v.x, v.y);
    *reinterpret_cast<__half2*>(&dst[i + 2]) = __floats2half2_rn(v.z, v.w);
}

// ---------------------------------------------------------------------------
// Raw mma.sync GEMM: C[M,N] = A[M,1024] @ B[1024,N] + bias
// CTA tile 128x128, BK=64, 2-stage cp.async, 128 threads = 4 warps of 64x64.
// 2-stage (71.7KB smem) + reg cap 170 -> 3 CTAs/SM = 12 warps/SM.
// ---------------------------------------------------------------------------
#define GBK 64
#define LDA 72
#define LDB 136
#define ASTG (128 * LDA)
#define BSTG (GBK * LDB)
#define GEMM_SMEM ((2 * (ASTG + BSTG)) * 2)   // 71680 B -> 3 CTAs/SM

__device__ __forceinline__ void gemm_fill(
    const __half* __restrict__ A, const __half* __restrict__ B,
    __half* As, __half* Bs, int N, int m0, int n0, int k0, int tid)
{
    #pragma unroll
    for (int i = 0; i < 8; i++) {
        int idx = tid + i * 128;
        int r = idx >> 3, c = (idx & 7) * 8;
        cp_async16(&As[r * LDA + c], A + (size_t)(m0 + r) * DIM + k0 + c);
    }
    #pragma unroll
    for (int i = 0; i < 8; i++) {
        int idx = tid + i * 128;
        int r = idx >> 4, c = (idx & 15) * 8;
        cp_async16(&Bs[r * LDB + c], B + (size_t)(k0 + r) * N + n0 + c);
    }
}

__global__ __launch_bounds__(128, 3) void gemm_h16(
    const float* __restrict__ bias, float* __restrict__ C, int N, int mode)
{
    extern __shared__ __half hsm[];
    __half* Asm = hsm;                 // [2][ASTG]
    __half* Bsm = hsm + 2 * ASTG;      // [2][BSTG]

    const int tid  = threadIdx.x;
    const int warp = tid >> 5;
    const int lane = tid & 31;
    const int wm   = warp & 1;        // 64-row band
    const int wn   = warp >> 1;       // 64-col band
    const int g    = lane >> 2;
    const int t4   = lane & 3;
    const int sub  = lane >> 3;
    const int rr   = lane & 7;
    const int m0   = blockIdx.y * 128;
    const int n0   = blockIdx.x * 128;

    const __half* A = (mode == 1) ? g_xh : g_attn;
    const __half* B = (mode == 1) ? g_wqkvh : g_wouth;

    float acc[4][8][4];
    #pragma unroll
    for (int mt = 0; mt < 4; mt++)
        #pragma unroll
        for (int nt = 0; nt < 8; nt++)
            #pragma unroll
            for (int e = 0; e < 4; e++) acc[mt][nt][e] = 0.0f;

    const int nk = DIM / GBK;   // 16
    gemm_fill(A, B, Asm, Bsm, N, m0, n0, 0, tid);
    CP_COMMIT();
    gemm_fill(A, B, Asm + ASTG, Bsm + BSTG, N, m0, n0, GBK, tid);
    CP_COMMIT();

    for (int t = 0; t < nk; t++) {
        if (t < nk - 1) { CP_WAIT(1); } else { CP_WAIT(0); }
        __syncthreads();

        const __half* As = Asm + (t & 1) * ASTG;
        const __half* Bs = Bsm + (t & 1) * BSTG;

        #pragma unroll
        for (int ks = 0; ks < 4; ks++) {
            uint32_t Af[4][4];
            #pragma unroll
            for (int mt = 0; mt < 4; mt++) {
                uint32_t a = smem_addr(&As[(wm * 64 + mt * 16 + (sub & 1) * 8 + rr) * LDA
                                           + ks * 16 + (sub >> 1) * 8]);
                ldsm_x4(Af[mt], a);
            }
            uint32_t Bf[4][4];
            #pragma unroll
            for (int p = 0; p < 4; p++) {
                uint32_t a = smem_addr(&Bs[(ks * 16 + (sub & 1) * 8 + rr) * LDB
                                           + wn * 64 + p * 16 + (sub >> 1) * 8]);
                ldsm_x4_t(Bf[p], a);
            }
            #pragma unroll
            for (int mt = 0; mt < 4; mt++)
                #pragma unroll
                for (int p = 0; p < 4; p++) {
                    mma_16816(acc[mt][2 * p],     Af[mt], &Bf[p][0]);
                    mma_16816(acc[mt][2 * p + 1], Af[mt], &Bf[p][2]);
                }
        }

        // All warps done reading this stage before it is refilled.
        __syncthreads();
        if (t + 2 < nk) {
            gemm_fill(A, B, Asm + (t & 1) * ASTG, Bsm + (t & 1) * BSTG,
                      N, m0, n0, (t + 2) * GBK, tid);
            CP_COMMIT();
        }
    }

    if (mode == 1) {
        #pragma unroll
        for (int nt = 0; nt < 8; nt++) {
            const int gn = n0 + wn * 64 + nt * 8 + 2 * t4;
            const int which = gn >> 10;
            const int d = gn & 1023;
            const int h = d >> 6;
            const int hd = d & 63;
            const float scale = (which == 0) ? 0.125f : 1.0f;
            const float b0 = bias[gn] * scale;
            const float b1 = bias[gn + 1] * scale;
            #pragma unroll
            for (int mt = 0; mt < 4; mt++) {
                int r0 = m0 + wm * 64 + mt * 16 + g;
                int bb = r0 >> 11;
                int ss = r0 & 2047;
                __half* d0 = &g_qkv[((((size_t)which * BATCH + bb) * HEADS + h) * SEQ + ss) * HDIM + hd];
                __half* d1 = &g_qkv[((((size_t)which * BATCH + bb) * HEADS + h) * SEQ + ss + 8) * HDIM + hd];
                *reinterpret_cast<uint32_t*>(d0) =
                    pack_h2(acc[mt][nt][0] * scale + b0, acc[mt][nt][1] * scale + b1);
                *reinterpret_cast<uint32_t*>(d1) =
                    pack_h2(acc[mt][nt][2] * scale + b0, acc[mt][nt][3] * scale + b1);
            }
        }
    } else {
        #pragma unroll
        for (int nt = 0; nt < 8; nt++) {
            const int gn = n0 + wn * 64 + nt * 8 + 2 * t4;
            const float b0 = bias[gn];
            const float b1 = bias[gn + 1];
            #pragma unroll
            for (int mt = 0; mt < 4; mt++) {
                int r0 = m0 + wm * 64 + mt * 16 + g;
                float2 v0 = { acc[mt][nt][0] + b0, acc[mt][nt][1] + b1 };
                float2 v1 = { acc[mt][nt][2] + b0, acc[mt][nt][3] + b1 };
                *reinterpret_cast<float2*>(&C[(size_t)r0 * N + gn]) = v0;
                *reinterpret_cast<float2*>(&C[(size_t)(r0 + 8) * N + gn]) = v1;
            }
        }
    }
}

// ---------------------------------------------------------------------------
// Register-resident FA2 flash attention (unchanged from R7/R8).
// ---------------------------------------------------------------------------
#define FST 72   // smem stride in halves
#define FLASH_SMEM ((128 * FST + 4 * 64 * FST) * 2)   // 55296 B

__global__ __launch_bounds__(128) void flash_attn(const int* __restrict__ flag_ptr)
{
    extern __shared__ __half fsm[];
    __half* Qs = fsm;
    __half* Ks0 = Qs + 128 * FST;
    __half* Vs0 = Ks0 + 2 * 64 * FST;

    const int qt = blockIdx.x;
    const int bh = blockIdx.y;
    const int b  = bh >> 4;
    const int h  = bh & 15;
    const int tid  = threadIdx.x;
    const int w    = tid >> 5;
    const int lane = tid & 31;
    const int g    = lane >> 2;
    const int t4   = lane & 3;
    const int sub  = lane >> 3;
    const int rr   = lane & 7;

    const __half* qg = g_qkv + (((size_t)b * HEADS + h) * SEQ + qt * 128) * HDIM;
    #pragma unroll
    for (int i = 0; i < 8; i++) {
        int idx = tid + i * 128;
        int r = idx >> 3, c = (idx & 7) * 8;
        *reinterpret_cast<uint4*>(&Qs[r * FST + c]) =
            *reinterpret_cast<const uint4*>(qg + r * 64 + c);
    }
    __syncthreads();

    uint32_t QA[2][4][4];
    #pragma unroll
    for (int mt = 0; mt < 2; mt++)
        #pragma unroll
        for (int c = 0; c < 4; c++) {
            uint32_t a = smem_addr(&Qs[(w * 32 + mt * 16 + (sub & 1) * 8 + rr) * FST
                                       + c * 16 + (sub >> 1) * 8]);
            ldsm_x4(QA[mt][c], a);
        }

    float O[2][8][4];
    #pragma unroll
    for (int mt = 0; mt < 2; mt++)
        #pragma unroll
        for (int j = 0; j < 8; j++)
            #pragma unroll
            for (int e = 0; e < 4; e++) O[mt][j][e] = 0.0f;
    float mst[2][2] = { { -1e30f, -1e30f }, { -1e30f, -1e30f } };
    float lst[2][2] = { { 0.0f, 0.0f }, { 0.0f, 0.0f } };

    const int causal = *flag_ptr;
    const int ktmax = causal ? (2 * qt + 1) : (SEQ / 64 - 1);
    const int qrow[2] = { qt * 128 + w * 32 + g, qt * 128 + w * 32 + 16 + g };
    const int wrow_min = qt * 128 + w * 32;
    const int wrow_max = wrow_min + 31;

    const __half* kgbase = g_qkv + ((((size_t)1 * BATCH + b) * HEADS + h) * SEQ) * HDIM;
    const __half* vgbase = g_qkv + ((((size_t)2 * BATCH + b) * HEADS + h) * SEQ) * HDIM;

    #pragma unroll
    for (int i = 0; i < 4; i++) {
        int idx = tid + i * 128;
        int r = idx >> 3, c = (idx & 7) * 8;
        cp_async16(&Ks0[r * FST + c], kgbase + r * 64 + c);
        cp_async16(&Vs0[r * FST + c], vgbase + r * 64 + c);
    }
    CP_COMMIT();

    for (int kt = 0; kt <= ktmax; kt++) {
        if (kt + 1 <= ktmax) {
            const __half* kg = kgbase + (size_t)(kt + 1) * 64 * HDIM;
            const __half* vg = vgbase + (size_t)(kt + 1) * 64 * HDIM;
            int nb = (kt + 1) & 1;
            #pragma unroll
            for (int i = 0; i < 4; i++) {
                int idx = tid + i * 128;
                int r = idx >> 3, c = (idx & 7) * 8;
                cp_async16(&Ks0[nb * 64 * FST + r * FST + c], kg + r * 64 + c);
                cp_async16(&Vs0[nb * 64 * FST + r * FST + c], vg + r * 64 + c);
            }
            CP_COMMIT();
            CP_WAIT(1);
        } else {
            CP_WAIT(0);
        }
        __syncthreads();

        if (!causal || kt * 64 <= wrow_max) {
            const __half* Kb = Ks0 + (kt & 1) * 64 * FST;
            const __half* Vb = Vs0 + (kt & 1) * 64 * FST;

            float S[2][8][4];
            #pragma unroll
            for (int mt = 0; mt < 2; mt++)
                #pragma unroll
                for (int j = 0; j < 8; j++)
                    #pragma unroll
                    for (int e = 0; e < 4; e++) S[mt][j][e] = 0.0f;

            #pragma unroll
            for (int p = 0; p < 4; p++) {
                #pragma unroll
                for (int c = 0; c < 4; c++) {
                    uint32_t Bf[4];
                    uint32_t a = smem_addr(&Kb[((2 * p + (sub >> 1)) * 8 + rr) * FST
                                               + c * 16 + (sub & 1) * 8]);
                    ldsm_x4(Bf, a);
                    #pragma unroll
                    for (int mt = 0; mt < 2; mt++) {
                        mma_16816(S[mt][2 * p],     QA[mt][c], &Bf[0]);
                        mma_16816(S[mt][2 * p + 1], QA[mt][c], &Bf[2]);
                    }
                }
            }

            if (causal && kt * 64 + 63 > wrow_min) {
                #pragma unroll
                for (int mt = 0; mt < 2; mt++)
                    #pragma unroll
                    for (int j = 0; j < 8; j++) {
                        int col = kt * 64 + j * 8 + 2 * t4;
                        if (col > qrow[mt])         S[mt][j][0] = -1e30f;
                        if (col + 1 > qrow[mt])     S[mt][j][1] = -1e30f;
                        if (col > qrow[mt] + 8)     S[mt][j][2] = -1e30f;
                        if (col + 1 > qrow[mt] + 8) S[mt][j][3] = -1e30f;
                    }
            }

            #pragma unroll
            for (int mt = 0; mt < 2; mt++) {
                float mx0 = -1e30f, mx1 = -1e30f;
                #pragma unroll
                for (int j = 0; j < 8; j++) {
                    mx0 = fmaxf(mx0, fmaxf(S[mt][j][0], S[mt][j][1]));
                    mx1 = fmaxf(mx1, fmaxf(S[mt][j][2], S[mt][j][3]));
                }
                mx0 = fmaxf(mx0, __shfl_xor_sync(0xffffffffu, mx0, 1));
                mx0 = fmaxf(mx0, __shfl_xor_sync(0xffffffffu, mx0, 2));
                mx1 = fmaxf(mx1, __shfl_xor_sync(0xffffffffu, mx1, 1));
                mx1 = fmaxf(mx1, __shfl_xor_sync(0xffffffffu, mx1, 2));

                float mn0 = fmaxf(mst[mt][0], mx0);
                float mn1 = fmaxf(mst[mt][1], mx1);
                float a0 = __expf(mst[mt][0] - mn0);
                float a1 = __expf(mst[mt][1] - mn1);

                float s0 = 0.0f, s1 = 0.0f;
                #pragma unroll
                for (int j = 0; j < 8; j++) {
                    S[mt][j][0] = __expf(S[mt][j][0] - mn0);
                    S[mt][j][1] = __expf(S[mt][j][1] - mn0);
                    S[mt][j][2] = __expf(S[mt][j][2] - mn1);
                    S[mt][j][3] = __expf(S[mt][j][3] - mn1);
                    s0 += S[mt][j][0] + S[mt][j][1];
                    s1 += S[mt][j][2] + S[mt][j][3];
                }
                s0 += __shfl_xor_sync(0xffffffffu, s0, 1);
                s0 += __shfl_xor_sync(0xffffffffu, s0, 2);
                s1 += __shfl_xor_sync(0xffffffffu, s1, 1);
                s1 += __shfl_xor_sync(0xffffffffu, s1, 2);

                lst[mt][0] = lst[mt][0] * a0 + s0;
                lst[mt][1] = lst[mt][1] * a1 + s1;
                mst[mt][0] = mn0;
                mst[mt][1] = mn1;

                #pragma unroll
                for (int j = 0; j < 8; j++) {
                    O[mt][j][0] *= a0; O[mt][j][1] *= a0;
                    O[mt][j][2] *= a1; O[mt][j][3] *= a1;
                }
            }

            #pragma unroll
            for (int c = 0; c < 4; c++) {
                uint32_t PA[2][4];
                #pragma unroll
                for (int mt = 0; mt < 2; mt++) {
                    PA[mt][0] = pack_h2(S[mt][2 * c][0],     S[mt][2 * c][1]);
                    PA[mt][1] = pack_h2(S[mt][2 * c][2],     S[mt][2 * c][3]);
                    PA[mt][2] = pack_h2(S[mt][2 * c + 1][0], S[mt][2 * c + 1][1]);
                    PA[mt][3] = pack_h2(S[mt][2 * c + 1][2], S[mt][2 * c + 1][3]);
                }
                #pragma unroll
                for (int jj = 0; jj < 8; jj += 2) {
                    uint32_t Bf[4];
                    uint32_t a = smem_addr(&Vb[(c * 16 + (sub & 1) * 8 + rr) * FST
                                               + (jj + (sub >> 1)) * 8]);
                    ldsm_x4_t(Bf, a);
                    #pragma unroll
                    for (int mt = 0; mt < 2; mt++) {
                        mma_16816(O[mt][jj],     PA[mt], &Bf[0]);
                        mma_16816(O[mt][jj + 1], PA[mt], &Bf[2]);
                    }
                }
            }
        }
        __syncthreads();
    }

    #pragma unroll
    for (int mt = 0; mt < 2; mt++) {
        float inv0 = 1.0f / lst[mt][0];
        float inv1 = 1.0f / lst[mt][1];
        __half* d0 = g_attn + ((size_t)b * SEQ + qrow[mt]) * DIM + h * HDIM;
        __half* d1 = g_attn + ((size_t)b * SEQ + qrow[mt] + 8) * DIM + h * HDIM;
        #pragma unroll
        for (int j = 0; j < 8; j++) {
            int hd = j * 8 + 2 * t4;
            *reinterpret_cast<uint32_t*>(d0 + hd) = pack_h2(O[mt][j][0] * inv0, O[mt][j][1] * inv0);
            *reinterpret_cast<uint32_t*>(d1 + hd) = pack_h2(O[mt][j][2] * inv1, O[mt][j][3] * inv1);
        }
    }
}

// ---------------------------------------------------------------------------
extern "C" void kernel_launch(void* const* d_in, const int* in_sizes, int n_in,
                              void* d_out, int out_size)
{
    const float* x     = (const float*)d_in[0];
    const float* Wqkv  = (const float*)d_in[1];
    const float* bqkv  = (const float*)d_in[2];
    const float* Wout  = (const float*)d_in[3];
    const float* bout  = (const float*)d_in[4];
    const int*   flag  = (const int*)d_in[5];
    float*       out   = (float*)d_out;

    cudaFuncSetAttribute(gemm_h16, cudaFuncAttributeMaxDynamicSharedMemorySize, GEMM_SMEM);
    cudaFuncSetAttribute(flash_attn, cudaFuncAttributeMaxDynamicSharedMemorySize, FLASH_SMEM);

    convert_all_kernel<<<12288, 256>>>(x, Wqkv, Wout);

    dim3 g1(3 * DIM / 128, MROWS / 128);   // (24, 64)
    gemm_h16<<<g1, 128, GEMM_SMEM>>>(bqkv, nullptr, 3 * DIM, 1);

    dim3 g2(SEQ / 128, BATCH * HEADS);     // (16, 64)
    flash_attn<<<g2, 128, FLASH_SMEM>>>(flag);

    dim3 g3(DIM / 128, MROWS / 128);       // (8, 64)
    gemm_h16<<<g3, 128, GEMM_SMEM>>>(bout, out, DIM, 2);
}